// round 3
// baseline (speedup 1.0000x reference)
#include <cuda_runtime.h>

// Multi-scale deformable attention, fully fused (round 3).
// Fixed constants: BS=2, NQ=32768, C=128, NH=1, NL=2, NP=8
//   level 0: H=128,W=256,start=0 ; level 1: H=64,W=128,start=32768 ; NV=40960

namespace {

constexpr int BSZ   = 2;
constexpr int NQ    = 32768;
constexpr int CH    = 128;
constexpr int NV    = 40960;
constexpr int NSAMP = 16;   // NL*NP
constexpr int NOFF  = 32;   // NL*NP*2
constexpr int WARPS = 8;    // warps per CTA
constexpr int QPW   = 8;    // queries per warp

__global__ void __launch_bounds__(WARPS * 32, 4) msda_fused(
    const float* __restrict__ query,
    const float* __restrict__ value,
    const float* __restrict__ qloc,
    const float* __restrict__ Woff,
    const float* __restrict__ boff,
    const float* __restrict__ Wattn,
    const float* __restrict__ battn,
    const float* __restrict__ Wout,
    const float* __restrict__ bout,
    float* __restrict__ out)
{
    __shared__ float sWoff[CH * NOFF];         // 16 KB
    __shared__ float sWattn[CH * NSAMP];       //  8 KB
    __shared__ float sboff[NOFF];
    __shared__ float sbattn[NSAMP];
    // Per-warp scratch, query-major [qq][k].
    // Phase A: holds the 8 query vectors.  Phase B overwrites each row with the
    // sampled vector (projections are fully done by then).  Phase C reads rows.
    __shared__ float ubuf[WARPS][QPW][CH];     // 32 KB

    const int tid = threadIdx.x;

    for (int i = tid; i < CH * NOFF; i += blockDim.x)  sWoff[i]  = Woff[i];
    for (int i = tid; i < CH * NSAMP; i += blockDim.x) sWattn[i] = Wattn[i];
    if (tid < NOFF)  sboff[tid]  = boff[tid];
    if (tid < NSAMP) sbattn[tid] = battn[tid];
    __syncthreads();

    const int warp = tid >> 5;
    const int lane = tid & 31;
    const int j16  = lane & 15;
    const int q0   = (blockIdx.x * WARPS + warp) * QPW;   // first query of this warp

    float (*ub)[CH] = ubuf[warp];

    // ---------------- Phase A: stage 8 query vectors, batched projections ---
    #pragma unroll
    for (int qq = 0; qq < QPW; qq++)
        ((float4*)ub[qq])[lane] =
            ((const float4*)(query + (size_t)(q0 + qq) * CH))[lane];
    __syncwarp();

    float offr[QPW], lg[QPW];
    #pragma unroll
    for (int qq = 0; qq < QPW; qq++) { offr[qq] = sboff[lane]; lg[qq] = sbattn[j16]; }

    #pragma unroll 4
    for (int k = 0; k < CH; k += 4) {
        const float wo0 = sWoff[(k + 0) * NOFF + lane];
        const float wo1 = sWoff[(k + 1) * NOFF + lane];
        const float wo2 = sWoff[(k + 2) * NOFF + lane];
        const float wo3 = sWoff[(k + 3) * NOFF + lane];
        const float wa0 = sWattn[(k + 0) * NSAMP + j16];
        const float wa1 = sWattn[(k + 1) * NSAMP + j16];
        const float wa2 = sWattn[(k + 2) * NSAMP + j16];
        const float wa3 = sWattn[(k + 3) * NSAMP + j16];
        #pragma unroll
        for (int qq = 0; qq < QPW; qq++) {
            const float4 qv = *(const float4*)&ub[qq][k];   // broadcast
            offr[qq] = fmaf(qv.x, wo0, offr[qq]);
            offr[qq] = fmaf(qv.y, wo1, offr[qq]);
            offr[qq] = fmaf(qv.z, wo2, offr[qq]);
            offr[qq] = fmaf(qv.w, wo3, offr[qq]);
            lg[qq] = fmaf(qv.x, wa0, lg[qq]);
            lg[qq] = fmaf(qv.y, wa1, lg[qq]);
            lg[qq] = fmaf(qv.z, wa2, lg[qq]);
            lg[qq] = fmaf(qv.w, wa3, lg[qq]);
        }
    }
    __syncwarp();

    // ---------------- Phase B: softmax + bilinear sampling per query --------
    #pragma unroll 1
    for (int qq = 0; qq < QPW; qq++) {
        const int qi = q0 + qq;
        const int b  = qi >> 15;                           // NQ = 32768

        // softmax over 16 samples (lanes 16..31 hold a duplicate copy)
        float l0 = lg[qq];
        float m = l0;
        #pragma unroll
        for (int o = 8; o >= 1; o >>= 1)
            m = fmaxf(m, __shfl_xor_sync(0xffffffffu, m, o));
        const float e = __expf(l0 - m);
        float se = e;
        #pragma unroll
        for (int o = 8; o >= 1; o >>= 1)
            se += __shfl_xor_sync(0xffffffffu, se, o);
        const float aw = e / se;

        const float  myoff = offr[qq];
        const float4 lv    = *(const float4*)(qloc + (size_t)qi * 4); // [l0.x,l0.y,l1.x,l1.y]
        const float* vbase = value + (size_t)b * NV * CH;

        float ac0 = 0.f, ac1 = 0.f, ac2 = 0.f, ac3 = 0.f;

        #pragma unroll
        for (int s = 0; s < NSAMP; s++) {
            const int l      = s >> 3;
            const int Hl     = l ? 64 : 128;
            const int Wl     = l ? 128 : 256;
            const int startl = l ? 32768 : 0;

            const float ox  = __shfl_sync(0xffffffffu, myoff, 2 * s);
            const float oy  = __shfl_sync(0xffffffffu, myoff, 2 * s + 1);
            const float aws = __shfl_sync(0xffffffffu, aw, s);

            const float x = (l ? lv.z : lv.x) * (float)Wl + ox - 0.5f;
            const float y = (l ? lv.w : lv.y) * (float)Hl + oy - 0.5f;
            const float xf = floorf(x), yf = floorf(y);
            const int   x0 = (int)xf,   y0 = (int)yf;
            const float lx = x - xf,    ly = y - yf;

            const float w00 = (1.f - lx) * (1.f - ly) * aws;
            const float w10 = lx * (1.f - ly) * aws;
            const float w01 = (1.f - lx) * ly * aws;
            const float w11 = lx * ly * aws;

            #pragma unroll
            for (int c = 0; c < 4; c++) {
                const int ix = x0 + (c & 1);
                const int iy = y0 + (c >> 1);
                const float w = (c == 0) ? w00 : (c == 1) ? w10 : (c == 2) ? w01 : w11;
                if ((unsigned)ix < (unsigned)Wl && (unsigned)iy < (unsigned)Hl) {
                    const float4 v =
                        ((const float4*)(vbase + (size_t)(startl + iy * Wl + ix) * CH))[lane];
                    ac0 = fmaf(w, v.x, ac0);
                    ac1 = fmaf(w, v.y, ac1);
                    ac2 = fmaf(w, v.z, ac2);
                    ac3 = fmaf(w, v.w, ac3);
                }
            }
        }

        // contiguous, conflict-free STS.128 (overwrites the now-dead query row)
        ((float4*)ub[qq])[lane] = make_float4(ac0, ac1, ac2, ac3);
    }
    __syncwarp();

    // ---------------- Phase C: output projection, all 8 queries in one pass -
    // lane owns output columns [lane*4, lane*4+4); W_out row stream amortized 8x
    const float4 bo = ((const float4*)bout)[lane];
    float4 a[QPW];
    #pragma unroll
    for (int qq = 0; qq < QPW; qq++) a[qq] = bo;

    #pragma unroll 4
    for (int k = 0; k < CH; k += 2) {
        const float4 w0 = ((const float4*)(Wout + (size_t)(k + 0) * CH))[lane];
        const float4 w1 = ((const float4*)(Wout + (size_t)(k + 1) * CH))[lane];
        #pragma unroll
        for (int qq = 0; qq < QPW; qq++) {
            const float2 sv = *(const float2*)&ub[qq][k];   // broadcast LDS.64
            a[qq].x = fmaf(sv.x, w0.x, a[qq].x);
            a[qq].y = fmaf(sv.x, w0.y, a[qq].y);
            a[qq].z = fmaf(sv.x, w0.z, a[qq].z);
            a[qq].w = fmaf(sv.x, w0.w, a[qq].w);
            a[qq].x = fmaf(sv.y, w1.x, a[qq].x);
            a[qq].y = fmaf(sv.y, w1.y, a[qq].y);
            a[qq].z = fmaf(sv.y, w1.z, a[qq].z);
            a[qq].w = fmaf(sv.y, w1.w, a[qq].w);
        }
    }

    #pragma unroll
    for (int qq = 0; qq < QPW; qq++)
        ((float4*)(out + (size_t)(q0 + qq) * CH))[lane] = a[qq];
}

} // namespace

extern "C" void kernel_launch(void* const* d_in, const int* in_sizes, int n_in,
                              void* d_out, int out_size)
{
    const float* query = (const float*)d_in[0];
    const float* value = (const float*)d_in[1];
    const float* qloc  = (const float*)d_in[2];
    const float* Woff  = (const float*)d_in[5];
    const float* boff  = (const float*)d_in[6];
    const float* Wattn = (const float*)d_in[7];
    const float* battn = (const float*)d_in[8];
    const float* Wout  = (const float*)d_in[9];
    const float* bout  = (const float*)d_in[10];

    constexpr int total_warps = (BSZ * NQ) / QPW;    // 8192
    constexpr int blocks = total_warps / WARPS;      // 1024
    msda_fused<<<blocks, WARPS * 32>>>(query, value, qloc, Woff, boff,
                                       Wattn, battn, Wout, bout, (float*)d_out);
}

// round 4
// speedup vs baseline: 1.4978x; 1.4978x over previous
#include <cuda_runtime.h>

// Multi-scale deformable attention, fully fused (round 4).
// Fixed constants: BS=2, NQ=32768, C=128, NH=1, NL=2, NP=8
//   level 0: H=128,W=256,start=0 ; level 1: H=64,W=128,start=32768 ; NV=40960

namespace {

constexpr int BSZ   = 2;
constexpr int NQ    = 32768;
constexpr int CH    = 128;
constexpr int NV    = 40960;
constexpr int NSAMP = 16;   // NL*NP
constexpr int NOFF  = 32;   // NL*NP*2
constexpr int WARPS = 8;    // warps per CTA
constexpr int QPW   = 4;    // queries per warp

__global__ void __launch_bounds__(WARPS * 32, 4) msda_fused(
    const float* __restrict__ query,
    const float* __restrict__ value,
    const float* __restrict__ qloc,
    const float* __restrict__ Woff,
    const float* __restrict__ boff,
    const float* __restrict__ Wattn,
    const float* __restrict__ battn,
    const float* __restrict__ Wout,
    const float* __restrict__ bout,
    float* __restrict__ out)
{
    __shared__ float sWoff[CH * NOFF];         // 16 KB
    __shared__ float sWattn[CH * NSAMP];       //  8 KB
    __shared__ float sboff[NOFF];
    __shared__ float sbattn[NSAMP];
    // Per-warp scratch, query-major [qq][k] (conflict-free rows).
    // Phase A: the 4 query vectors.  Phase B: overwritten with sampled vectors.
    __shared__ float ubuf[WARPS][QPW][CH];     // 16 KB

    const int tid = threadIdx.x;

    for (int i = tid; i < CH * NOFF; i += blockDim.x)  sWoff[i]  = Woff[i];
    for (int i = tid; i < CH * NSAMP; i += blockDim.x) sWattn[i] = Wattn[i];
    if (tid < NOFF)  sboff[tid]  = boff[tid];
    if (tid < NSAMP) sbattn[tid] = battn[tid];
    __syncthreads();

    const int warp = tid >> 5;
    const int lane = tid & 31;
    const int j16  = lane & 15;
    const int q0   = (blockIdx.x * WARPS + warp) * QPW;   // first query of this warp

    float (*ub)[CH] = ubuf[warp];

    // ---------------- Phase A: stage 4 query vectors, batched projections ---
    #pragma unroll
    for (int qq = 0; qq < QPW; qq++)
        ((float4*)ub[qq])[lane] =
            ((const float4*)(query + (size_t)(q0 + qq) * CH))[lane];
    __syncwarp();

    float offr[QPW], lg[QPW];
    #pragma unroll
    for (int qq = 0; qq < QPW; qq++) { offr[qq] = sboff[lane]; lg[qq] = sbattn[j16]; }

    #pragma unroll 4
    for (int k = 0; k < CH; k += 4) {
        const float wo0 = sWoff[(k + 0) * NOFF + lane];
        const float wo1 = sWoff[(k + 1) * NOFF + lane];
        const float wo2 = sWoff[(k + 2) * NOFF + lane];
        const float wo3 = sWoff[(k + 3) * NOFF + lane];
        const float wa0 = sWattn[(k + 0) * NSAMP + j16];
        const float wa1 = sWattn[(k + 1) * NSAMP + j16];
        const float wa2 = sWattn[(k + 2) * NSAMP + j16];
        const float wa3 = sWattn[(k + 3) * NSAMP + j16];
        #pragma unroll
        for (int qq = 0; qq < QPW; qq++) {
            const float4 qv = *(const float4*)&ub[qq][k];   // broadcast LDS.128
            offr[qq] = fmaf(qv.x, wo0, offr[qq]);
            offr[qq] = fmaf(qv.y, wo1, offr[qq]);
            offr[qq] = fmaf(qv.z, wo2, offr[qq]);
            offr[qq] = fmaf(qv.w, wo3, offr[qq]);
            lg[qq] = fmaf(qv.x, wa0, lg[qq]);
            lg[qq] = fmaf(qv.y, wa1, lg[qq]);
            lg[qq] = fmaf(qv.z, wa2, lg[qq]);
            lg[qq] = fmaf(qv.w, wa3, lg[qq]);
        }
    }
    __syncwarp();

    // ---------------- Phase B: softmax + bilinear sampling per query --------
    #pragma unroll 1
    for (int qq = 0; qq < QPW; qq++) {
        const int qi = q0 + qq;
        const int b  = qi >> 15;                           // NQ = 32768

        // softmax over 16 samples (lanes 16..31 hold a duplicate copy)
        float l0 = lg[qq];
        float m = l0;
        #pragma unroll
        for (int o = 8; o >= 1; o >>= 1)
            m = fmaxf(m, __shfl_xor_sync(0xffffffffu, m, o));
        const float e = __expf(l0 - m);
        float se = e;
        #pragma unroll
        for (int o = 8; o >= 1; o >>= 1)
            se += __shfl_xor_sync(0xffffffffu, se, o);
        const float aw = e / se;

        const float  myoff = offr[qq];
        const float4 lv    = *(const float4*)(qloc + (size_t)qi * 4); // [l0x,l0y,l1x,l1y]
        const float* vbase = value + (size_t)b * NV * CH;

        float ac0 = 0.f, ac1 = 0.f, ac2 = 0.f, ac3 = 0.f;

        #pragma unroll
        for (int s = 0; s < NSAMP; s++) {
            const int l      = s >> 3;
            const int Hl     = l ? 64 : 128;
            const int Wl     = l ? 128 : 256;
            const int startl = l ? 32768 : 0;

            const float ox  = __shfl_sync(0xffffffffu, myoff, 2 * s);
            const float oy  = __shfl_sync(0xffffffffu, myoff, 2 * s + 1);
            const float aws = __shfl_sync(0xffffffffu, aw, s);

            const float x = (l ? lv.z : lv.x) * (float)Wl + ox - 0.5f;
            const float y = (l ? lv.w : lv.y) * (float)Hl + oy - 0.5f;
            const float xf = floorf(x), yf = floorf(y);
            const int   x0 = (int)xf,   y0 = (int)yf;
            const float lx = x - xf,    ly = y - yf;

            const float w00 = (1.f - lx) * (1.f - ly) * aws;
            const float w10 = lx * (1.f - ly) * aws;
            const float w01 = (1.f - lx) * ly * aws;
            const float w11 = lx * ly * aws;

            #pragma unroll
            for (int c = 0; c < 4; c++) {
                const int ix = x0 + (c & 1);
                const int iy = y0 + (c >> 1);
                const float w = (c == 0) ? w00 : (c == 1) ? w10 : (c == 2) ? w01 : w11;
                if ((unsigned)ix < (unsigned)Wl && (unsigned)iy < (unsigned)Hl) {
                    const float4 v =
                        ((const float4*)(vbase + (size_t)(startl + iy * Wl + ix) * CH))[lane];
                    ac0 = fmaf(w, v.x, ac0);
                    ac1 = fmaf(w, v.y, ac1);
                    ac2 = fmaf(w, v.z, ac2);
                    ac3 = fmaf(w, v.w, ac3);
                }
            }
        }

        // contiguous, conflict-free STS.128 (overwrites the now-dead query row)
        ((float4*)ub[qq])[lane] = make_float4(ac0, ac1, ac2, ac3);
    }
    __syncwarp();

    // ---------------- Phase C: output projection, 4 queries in one pass -----
    // lane owns output columns [lane*4, lane*4+4); W_out stream amortized 4x
    const float4 bo = ((const float4*)bout)[lane];
    float4 a[QPW];
    #pragma unroll
    for (int qq = 0; qq < QPW; qq++) a[qq] = bo;

    #pragma unroll 4
    for (int k = 0; k < CH; k += 2) {
        const float4 w0 = ((const float4*)(Wout + (size_t)(k + 0) * CH))[lane];
        const float4 w1 = ((const float4*)(Wout + (size_t)(k + 1) * CH))[lane];
        #pragma unroll
        for (int qq = 0; qq < QPW; qq++) {
            const float2 sv = *(const float2*)&ub[qq][k];   // broadcast LDS.64
            a[qq].x = fmaf(sv.x, w0.x, a[qq].x);
            a[qq].y = fmaf(sv.x, w0.y, a[qq].y);
            a[qq].z = fmaf(sv.x, w0.z, a[qq].z);
            a[qq].w = fmaf(sv.x, w0.w, a[qq].w);
            a[qq].x = fmaf(sv.y, w1.x, a[qq].x);
            a[qq].y = fmaf(sv.y, w1.y, a[qq].y);
            a[qq].z = fmaf(sv.y, w1.z, a[qq].z);
            a[qq].w = fmaf(sv.y, w1.w, a[qq].w);
        }
    }

    #pragma unroll
    for (int qq = 0; qq < QPW; qq++)
        ((float4*)(out + (size_t)(q0 + qq) * CH))[lane] = a[qq];
}

} // namespace

extern "C" void kernel_launch(void* const* d_in, const int* in_sizes, int n_in,
                              void* d_out, int out_size)
{
    const float* query = (const float*)d_in[0];
    const float* value = (const float*)d_in[1];
    const float* qloc  = (const float*)d_in[2];
    const float* Woff  = (const float*)d_in[5];
    const float* boff  = (const float*)d_in[6];
    const float* Wattn = (const float*)d_in[7];
    const float* battn = (const float*)d_in[8];
    const float* Wout  = (const float*)d_in[9];
    const float* bout  = (const float*)d_in[10];

    constexpr int total_warps = (BSZ * NQ) / QPW;    // 16384
    constexpr int blocks = total_warps / WARPS;      // 2048
    msda_fused<<<blocks, WARPS * 32>>>(query, value, qloc, Woff, boff,
                                       Wattn, battn, Wout, bout, (float*)d_out);
}

// round 5
// speedup vs baseline: 1.5690x; 1.0475x over previous
#include <cuda_runtime.h>

// Multi-scale deformable attention, fully fused (round 5).
// Fixed constants: BS=2, NQ=32768, C=128, NH=1, NL=2, NP=8
//   level 0: H=128,W=256,start=0 ; level 1: H=64,W=128,start=32768 ; NV=40960

namespace {

constexpr int BSZ   = 2;
constexpr int NQ    = 32768;
constexpr int CH    = 128;
constexpr int NV    = 40960;
constexpr int NSAMP = 16;   // NL*NP
constexpr int NOFF  = 32;   // NL*NP*2
constexpr int WARPS = 8;    // warps per CTA
constexpr int QPW   = 4;    // queries per warp

__global__ void __launch_bounds__(WARPS * 32, 5) msda_fused(
    const float* __restrict__ query,
    const float* __restrict__ value,
    const float* __restrict__ qloc,
    const float* __restrict__ Woff,
    const float* __restrict__ boff,
    const float* __restrict__ Wattn,
    const float* __restrict__ battn,
    const float* __restrict__ Wout,
    const float* __restrict__ bout,
    float* __restrict__ out)
{
    __shared__ float sWoff[CH * NOFF];          // 16 KB (natural layout: [k][32])
    __shared__ float sWattn[CH * NSAMP];        //  8 KB
    __shared__ float sboff[NOFF];
    __shared__ float sbattn[NSAMP];
    // Per-warp scratch, query-major [qq][k] (conflict-free rows).
    __shared__ float ubuf[WARPS][QPW][CH];      // 16 KB
    // Per-warp sample records: [s][0..3]=corner byte-offsets (int bits),
    //                          [s][4..7]=aw-scaled corner weights.
    __shared__ float srec[WARPS][NSAMP][8];     //  4 KB

    const int tid = threadIdx.x;

    for (int i = tid; i < CH * NOFF; i += blockDim.x)  sWoff[i]  = Woff[i];
    for (int i = tid; i < CH * NSAMP; i += blockDim.x) sWattn[i] = Wattn[i];
    if (tid < NOFF)  sboff[tid]  = boff[tid];
    if (tid < NSAMP) sbattn[tid] = battn[tid];
    __syncthreads();

    const int warp = tid >> 5;
    const int lane = tid & 31;
    const int j16  = lane & 15;                 // sample owned by this lane
    const int q0   = (blockIdx.x * WARPS + warp) * QPW;
    const int b    = q0 >> 15;                  // same batch for all 4 queries

    float (*ub)[CH] = ubuf[warp];
    float (*rec)[8] = srec[warp];

    // ---------------- Phase A: stage 4 query vectors, batched projections ---
    // Lane j computes the (ox,oy) PAIR of sample j (columns 2j,2j+1 of W_off)
    // plus the attn logit of sample j.  Lanes 16-31 hold duplicates.
    #pragma unroll
    for (int qq = 0; qq < QPW; qq++)
        ((float4*)ub[qq])[lane] =
            ((const float4*)(query + (size_t)(q0 + qq) * CH))[lane];
    __syncwarp();

    float2 offa[QPW];
    float  lg[QPW];
    {
        const float2 b2 = *(const float2*)&sboff[2 * j16];
        #pragma unroll
        for (int qq = 0; qq < QPW; qq++) { offa[qq] = b2; lg[qq] = sbattn[j16]; }
    }

    #pragma unroll 4
    for (int k = 0; k < CH; k += 4) {
        const float2 wo0 = *(const float2*)&sWoff[(k + 0) * NOFF + 2 * j16];
        const float2 wo1 = *(const float2*)&sWoff[(k + 1) * NOFF + 2 * j16];
        const float2 wo2 = *(const float2*)&sWoff[(k + 2) * NOFF + 2 * j16];
        const float2 wo3 = *(const float2*)&sWoff[(k + 3) * NOFF + 2 * j16];
        const float wa0 = sWattn[(k + 0) * NSAMP + j16];
        const float wa1 = sWattn[(k + 1) * NSAMP + j16];
        const float wa2 = sWattn[(k + 2) * NSAMP + j16];
        const float wa3 = sWattn[(k + 3) * NSAMP + j16];
        #pragma unroll
        for (int qq = 0; qq < QPW; qq++) {
            const float4 qv = *(const float4*)&ub[qq][k];   // broadcast LDS.128
            offa[qq].x = fmaf(qv.x, wo0.x, offa[qq].x);
            offa[qq].y = fmaf(qv.x, wo0.y, offa[qq].y);
            offa[qq].x = fmaf(qv.y, wo1.x, offa[qq].x);
            offa[qq].y = fmaf(qv.y, wo1.y, offa[qq].y);
            offa[qq].x = fmaf(qv.z, wo2.x, offa[qq].x);
            offa[qq].y = fmaf(qv.z, wo2.y, offa[qq].y);
            offa[qq].x = fmaf(qv.w, wo3.x, offa[qq].x);
            offa[qq].y = fmaf(qv.w, wo3.y, offa[qq].y);
            lg[qq] = fmaf(qv.x, wa0, lg[qq]);
            lg[qq] = fmaf(qv.y, wa1, lg[qq]);
            lg[qq] = fmaf(qv.z, wa2, lg[qq]);
            lg[qq] = fmaf(qv.w, wa3, lg[qq]);
        }
    }

    // Level constants for the sample this lane owns.
    const int  l_own   = j16 >> 3;
    const int  Hl      = l_own ? 64 : 128;
    const int  Wl      = l_own ? 128 : 256;
    const int  startl  = l_own ? 32768 : 0;
    const char* vb = (const char*)(value + (size_t)b * NV * CH) + lane * 16;

    // ---------------- Phase B: per query: softmax, records, gather ----------
    #pragma unroll 1
    for (int qq = 0; qq < QPW; qq++) {
        const int qi = q0 + qq;

        __syncwarp();   // records of previous query fully consumed

        // softmax over 16 samples (lanes 16..31 duplicate)
        float l0 = lg[qq];
        float m = l0;
        #pragma unroll
        for (int o = 8; o >= 1; o >>= 1)
            m = fmaxf(m, __shfl_xor_sync(0xffffffffu, m, o));
        const float e = __expf(l0 - m);
        float se = e;
        #pragma unroll
        for (int o = 8; o >= 1; o >>= 1)
            se += __shfl_xor_sync(0xffffffffu, se, o);
        const float aw = e / se;            // weight of sample j16

        // Per-lane sample record (16 samples computed in parallel).
        {
            const float4 lv = *(const float4*)(qloc + (size_t)qi * 4);
            const float x = (l_own ? lv.z : lv.x) * (float)Wl + offa[qq].x - 0.5f;
            const float y = (l_own ? lv.w : lv.y) * (float)Hl + offa[qq].y - 0.5f;
            const float xf = floorf(x), yf = floorf(y);
            const int   x0 = (int)xf,   y0 = (int)yf;
            const float lx = x - xf,    ly = y - yf;

            const bool vx0 = (unsigned)x0 < (unsigned)Wl;
            const bool vx1 = (unsigned)(x0 + 1) < (unsigned)Wl;
            const bool vy0 = (unsigned)y0 < (unsigned)Hl;
            const bool vy1 = (unsigned)(y0 + 1) < (unsigned)Hl;

            const float w00 = (vx0 && vy0) ? (1.f - lx) * (1.f - ly) * aw : 0.f;
            const float w10 = (vx1 && vy0) ? lx * (1.f - ly) * aw : 0.f;
            const float w01 = (vx0 && vy1) ? (1.f - lx) * ly * aw : 0.f;
            const float w11 = (vx1 && vy1) ? lx * ly * aw : 0.f;

            const int cx0 = min(max(x0, 0), Wl - 1);
            const int cx1 = min(max(x0 + 1, 0), Wl - 1);
            const int cy0 = min(max(y0, 0), Hl - 1) * Wl + startl;
            const int cy1 = min(max(y0 + 1, 0), Hl - 1) * Wl + startl;

            // byte offsets of the 4 corner rows (CH*4 = 512 B per row)
            const int o00 = (cy0 + cx0) << 9;
            const int o10 = (cy0 + cx1) << 9;
            const int o01 = (cy1 + cx0) << 9;
            const int o11 = (cy1 + cx1) << 9;

            if (lane < NSAMP) {
                *(float4*)&rec[lane][0] = make_float4(
                    __int_as_float(o00), __int_as_float(o10),
                    __int_as_float(o01), __int_as_float(o11));
                *(float4*)&rec[lane][4] = make_float4(w00, w10, w01, w11);
            }
        }
        __syncwarp();

        // Gather: unconditional clamped loads, fully unrolled -> deep MLP.
        float ac0 = 0.f, ac1 = 0.f, ac2 = 0.f, ac3 = 0.f;
        #pragma unroll
        for (int s = 0; s < NSAMP; s++) {
            const float4 ro = *(const float4*)&rec[s][0];   // broadcast
            const float4 rw = *(const float4*)&rec[s][4];   // broadcast
            const float4 v00 = *(const float4*)(vb + __float_as_int(ro.x));
            const float4 v10 = *(const float4*)(vb + __float_as_int(ro.y));
            const float4 v01 = *(const float4*)(vb + __float_as_int(ro.z));
            const float4 v11 = *(const float4*)(vb + __float_as_int(ro.w));
            ac0 = fmaf(rw.x, v00.x, ac0); ac1 = fmaf(rw.x, v00.y, ac1);
            ac2 = fmaf(rw.x, v00.z, ac2); ac3 = fmaf(rw.x, v00.w, ac3);
            ac0 = fmaf(rw.y, v10.x, ac0); ac1 = fmaf(rw.y, v10.y, ac1);
            ac2 = fmaf(rw.y, v10.z, ac2); ac3 = fmaf(rw.y, v10.w, ac3);
            ac0 = fmaf(rw.z, v01.x, ac0); ac1 = fmaf(rw.z, v01.y, ac1);
            ac2 = fmaf(rw.z, v01.z, ac2); ac3 = fmaf(rw.z, v01.w, ac3);
            ac0 = fmaf(rw.w, v11.x, ac0); ac1 = fmaf(rw.w, v11.y, ac1);
            ac2 = fmaf(rw.w, v11.z, ac2); ac3 = fmaf(rw.w, v11.w, ac3);
        }

        // conflict-free STS.128 (overwrites the now-dead query row)
        ((float4*)ub[qq])[lane] = make_float4(ac0, ac1, ac2, ac3);
    }
    __syncwarp();

    // ---------------- Phase C: output projection, 4 queries in one pass -----
    const float4 bo = ((const float4*)bout)[lane];
    float4 a[QPW];
    #pragma unroll
    for (int qq = 0; qq < QPW; qq++) a[qq] = bo;

    #pragma unroll 4
    for (int k = 0; k < CH; k += 2) {
        const float4 w0 = ((const float4*)(Wout + (size_t)(k + 0) * CH))[lane];
        const float4 w1 = ((const float4*)(Wout + (size_t)(k + 1) * CH))[lane];
        #pragma unroll
        for (int qq = 0; qq < QPW; qq++) {
            const float2 sv = *(const float2*)&ub[qq][k];   // broadcast LDS.64
            a[qq].x = fmaf(sv.x, w0.x, a[qq].x);
            a[qq].y = fmaf(sv.x, w0.y, a[qq].y);
            a[qq].z = fmaf(sv.x, w0.z, a[qq].z);
            a[qq].w = fmaf(sv.x, w0.w, a[qq].w);
            a[qq].x = fmaf(sv.y, w1.x, a[qq].x);
            a[qq].y = fmaf(sv.y, w1.y, a[qq].y);
            a[qq].z = fmaf(sv.y, w1.z, a[qq].z);
            a[qq].w = fmaf(sv.y, w1.w, a[qq].w);
        }
    }

    #pragma unroll
    for (int qq = 0; qq < QPW; qq++)
        ((float4*)(out + (size_t)(q0 + qq) * CH))[lane] = a[qq];
}

} // namespace

extern "C" void kernel_launch(void* const* d_in, const int* in_sizes, int n_in,
                              void* d_out, int out_size)
{
    const float* query = (const float*)d_in[0];
    const float* value = (const float*)d_in[1];
    const float* qloc  = (const float*)d_in[2];
    const float* Woff  = (const float*)d_in[5];
    const float* boff  = (const float*)d_in[6];
    const float* Wattn = (const float*)d_in[7];
    const float* battn = (const float*)d_in[8];
    const float* Wout  = (const float*)d_in[9];
    const float* bout  = (const float*)d_in[10];

    constexpr int total_warps = (BSZ * NQ) / QPW;    // 16384
    constexpr int blocks = total_warps / WARPS;      // 2048
    msda_fused<<<blocks, WARPS * 32>>>(query, value, qloc, Woff, boff,
                                       Wattn, battn, Wout, bout, (float*)d_out);
}

// round 6
// speedup vs baseline: 1.7019x; 1.0847x over previous
#include <cuda_runtime.h>

// Multi-scale deformable attention, fully fused (round 6).
// Fixed constants: BS=2, NQ=32768, C=128, NH=1, NL=2, NP=8
//   level 0: H=128,W=256,start=0 ; level 1: H=64,W=128,start=32768 ; NV=40960

namespace {

constexpr int BSZ   = 2;
constexpr int NQ    = 32768;
constexpr int CH    = 128;
constexpr int NV    = 40960;
constexpr int NSAMP = 16;   // NL*NP
constexpr int NOFF  = 32;   // NL*NP*2
constexpr int WARPS = 8;    // warps per CTA
constexpr int QPW   = 4;    // queries per warp
constexpr int QPC   = WARPS * QPW;   // 32 queries per CTA

__global__ void __launch_bounds__(WARPS * 32, 4) msda_fused(
    const float* __restrict__ query,
    const float* __restrict__ value,
    const float* __restrict__ qloc,
    const float* __restrict__ Woff,
    const float* __restrict__ boff,
    const float* __restrict__ Wattn,
    const float* __restrict__ battn,
    const float* __restrict__ Wout,
    const float* __restrict__ bout,
    float* __restrict__ out)
{
    // Dual-use buffer (17 KB), padded stride 33 for conflict-free access:
    //  Phase A: row q = query vector of CTA-query q      (tbuf[q][k4] = ch 4k4..)
    //  Phase B: overwritten TRANSPOSED with sampled vecs (tbuf[k4][q] = ch 4k4..)
    __shared__ float4 tbuf[QPC][33];
    // Per-warp sample records: [s][0..3]=corner byte offsets, [4..7]=weights.
    __shared__ float  srec[WARPS][NSAMP][8];    // 4 KB

    const int tid  = threadIdx.x;
    const int warp = tid >> 5;
    const int lane = tid & 31;
    const int j16  = lane & 15;                 // sample owned by this lane
    const int qb   = blockIdx.x * QPC;          // first query of CTA
    const int q0   = qb + warp * QPW;           // first query of this warp
    const int b    = q0 >> 15;                  // batch (uniform within CTA)

    float (*rec)[8] = srec[warp];

    // ---------------- Phase A: stage queries + projections ------------------
    // Lane j computes (ox,oy) pair of sample j (cols 2j,2j+1 of W_off) and the
    // attn logit of sample j.  Lanes 16..31 duplicate.  Weights come straight
    // from GMEM (L1-resident rows: 128B / 64B per row, 1 wavefront each).
    #pragma unroll
    for (int qq = 0; qq < QPW; qq++)
        tbuf[warp * QPW + qq][lane] =
            ((const float4*)(query + (size_t)(q0 + qq) * CH))[lane];
    __syncwarp();

    float2 offa[QPW];
    float  lg[QPW];
    {
        const float2 b2 = *(const float2*)&boff[2 * j16];
        const float  ba = battn[j16];
        #pragma unroll
        for (int qq = 0; qq < QPW; qq++) { offa[qq] = b2; lg[qq] = ba; }
    }

    #pragma unroll 4
    for (int k4 = 0; k4 < CH / 4; k4++) {
        const int k = 4 * k4;
        const float2 wo0 = *(const float2*)&Woff[(k + 0) * NOFF + 2 * j16];
        const float2 wo1 = *(const float2*)&Woff[(k + 1) * NOFF + 2 * j16];
        const float2 wo2 = *(const float2*)&Woff[(k + 2) * NOFF + 2 * j16];
        const float2 wo3 = *(const float2*)&Woff[(k + 3) * NOFF + 2 * j16];
        const float wa0 = Wattn[(k + 0) * NSAMP + j16];
        const float wa1 = Wattn[(k + 1) * NSAMP + j16];
        const float wa2 = Wattn[(k + 2) * NSAMP + j16];
        const float wa3 = Wattn[(k + 3) * NSAMP + j16];
        #pragma unroll
        for (int qq = 0; qq < QPW; qq++) {
            const float4 qv = tbuf[warp * QPW + qq][k4];    // broadcast LDS.128
            offa[qq].x = fmaf(qv.x, wo0.x, offa[qq].x);
            offa[qq].y = fmaf(qv.x, wo0.y, offa[qq].y);
            offa[qq].x = fmaf(qv.y, wo1.x, offa[qq].x);
            offa[qq].y = fmaf(qv.y, wo1.y, offa[qq].y);
            offa[qq].x = fmaf(qv.z, wo2.x, offa[qq].x);
            offa[qq].y = fmaf(qv.z, wo2.y, offa[qq].y);
            offa[qq].x = fmaf(qv.w, wo3.x, offa[qq].x);
            offa[qq].y = fmaf(qv.w, wo3.y, offa[qq].y);
            lg[qq] = fmaf(qv.x, wa0, lg[qq]);
            lg[qq] = fmaf(qv.y, wa1, lg[qq]);
            lg[qq] = fmaf(qv.z, wa2, lg[qq]);
            lg[qq] = fmaf(qv.w, wa3, lg[qq]);
        }
    }
    __syncthreads();    // all query-vector reads done before transposed stores

    // Level constants for the sample this lane owns.
    const int  l_own  = j16 >> 3;
    const int  Hl     = l_own ? 64 : 128;
    const int  Wl     = l_own ? 128 : 256;
    const int  startl = l_own ? 32768 : 0;
    const char* vb = (const char*)(value + (size_t)b * NV * CH) + lane * 16;

    // ---------------- Phase B: softmax, sample records, gather --------------
    #pragma unroll 1
    for (int qq = 0; qq < QPW; qq++) {
        const int qi = q0 + qq;

        __syncwarp();   // records of previous query fully consumed

        // softmax over 16 samples (lanes 16..31 duplicate)
        float l0 = lg[qq];
        float m = l0;
        #pragma unroll
        for (int o = 8; o >= 1; o >>= 1)
            m = fmaxf(m, __shfl_xor_sync(0xffffffffu, m, o));
        const float e = __expf(l0 - m);
        float se = e;
        #pragma unroll
        for (int o = 8; o >= 1; o >>= 1)
            se += __shfl_xor_sync(0xffffffffu, se, o);
        const float aw = e / se;            // weight of sample j16

        // Per-lane sample record (16 samples in parallel).
        {
            const float4 lv = *(const float4*)(qloc + (size_t)qi * 4);
            const float x = (l_own ? lv.z : lv.x) * (float)Wl + offa[qq].x - 0.5f;
            const float y = (l_own ? lv.w : lv.y) * (float)Hl + offa[qq].y - 0.5f;
            const float xf = floorf(x), yf = floorf(y);
            const int   x0 = (int)xf,   y0 = (int)yf;
            const float lx = x - xf,    ly = y - yf;

            const bool vx0 = (unsigned)x0 < (unsigned)Wl;
            const bool vx1 = (unsigned)(x0 + 1) < (unsigned)Wl;
            const bool vy0 = (unsigned)y0 < (unsigned)Hl;
            const bool vy1 = (unsigned)(y0 + 1) < (unsigned)Hl;

            const float w00 = (vx0 && vy0) ? (1.f - lx) * (1.f - ly) * aw : 0.f;
            const float w10 = (vx1 && vy0) ? lx * (1.f - ly) * aw : 0.f;
            const float w01 = (vx0 && vy1) ? (1.f - lx) * ly * aw : 0.f;
            const float w11 = (vx1 && vy1) ? lx * ly * aw : 0.f;

            const int cx0 = min(max(x0, 0), Wl - 1);
            const int cx1 = min(max(x0 + 1, 0), Wl - 1);
            const int cy0 = min(max(y0, 0), Hl - 1) * Wl + startl;
            const int cy1 = min(max(y0 + 1, 0), Hl - 1) * Wl + startl;

            const int o00 = (cy0 + cx0) << 9;   // 512 B per value row
            const int o10 = (cy0 + cx1) << 9;
            const int o01 = (cy1 + cx0) << 9;
            const int o11 = (cy1 + cx1) << 9;

            if (lane < NSAMP) {
                *(float4*)&rec[lane][0] = make_float4(
                    __int_as_float(o00), __int_as_float(o10),
                    __int_as_float(o01), __int_as_float(o11));
                *(float4*)&rec[lane][4] = make_float4(w00, w10, w01, w11);
            }
        }
        __syncwarp();

        // Gather: unconditional clamped loads, fully unrolled (deep MLP).
        float ac0 = 0.f, ac1 = 0.f, ac2 = 0.f, ac3 = 0.f;
        #pragma unroll
        for (int s = 0; s < NSAMP; s++) {
            const float4 ro = *(const float4*)&rec[s][0];   // broadcast
            const float4 rw = *(const float4*)&rec[s][4];   // broadcast
            const float4 v00 = *(const float4*)(vb + __float_as_int(ro.x));
            const float4 v10 = *(const float4*)(vb + __float_as_int(ro.y));
            const float4 v01 = *(const float4*)(vb + __float_as_int(ro.z));
            const float4 v11 = *(const float4*)(vb + __float_as_int(ro.w));
            ac0 = fmaf(rw.x, v00.x, ac0); ac1 = fmaf(rw.x, v00.y, ac1);
            ac2 = fmaf(rw.x, v00.z, ac2); ac3 = fmaf(rw.x, v00.w, ac3);
            ac0 = fmaf(rw.y, v10.x, ac0); ac1 = fmaf(rw.y, v10.y, ac1);
            ac2 = fmaf(rw.y, v10.z, ac2); ac3 = fmaf(rw.y, v10.w, ac3);
            ac0 = fmaf(rw.z, v01.x, ac0); ac1 = fmaf(rw.z, v01.y, ac1);
            ac2 = fmaf(rw.z, v01.z, ac2); ac3 = fmaf(rw.z, v01.w, ac3);
            ac0 = fmaf(rw.w, v11.x, ac0); ac1 = fmaf(rw.w, v11.y, ac1);
            ac2 = fmaf(rw.w, v11.z, ac2); ac3 = fmaf(rw.w, v11.w, ac3);
        }

        // transposed stash: tbuf[k4=lane][query] = channels 4*lane..4*lane+3
        tbuf[lane][warp * QPW + qq] = make_float4(ac0, ac1, ac2, ac3);
    }
    __syncthreads();    // all sampled vectors visible CTA-wide

    // ---------------- Phase C: CTA-cooperative output projection ------------
    // Warp w owns output cols [16w,16w+16).  Lane tile: 4 queries x 4 cols.
    // W_out streamed once per CTA slice -> 16 wf/query instead of 128.
    {
        const int qg = lane >> 2;               // query group 0..7
        const int cg = lane & 3;                // col group  0..3
        const int colbase = warp * 16 + cg * 4;
        const int qrow = 4 * qg;

        const float4 bo = *(const float4*)&bout[colbase];
        float4 a0 = bo, a1 = bo, a2 = bo, a3 = bo;

        #pragma unroll 2
        for (int k4 = 0; k4 < CH / 4; k4++) {
            const float4 s0 = tbuf[k4][qrow + 0];
            const float4 s1 = tbuf[k4][qrow + 1];
            const float4 s2 = tbuf[k4][qrow + 2];
            const float4 s3 = tbuf[k4][qrow + 3];
            const float4 w0 = *(const float4*)&Wout[(4 * k4 + 0) * CH + colbase];
            const float4 w1 = *(const float4*)&Wout[(4 * k4 + 1) * CH + colbase];
            const float4 w2 = *(const float4*)&Wout[(4 * k4 + 2) * CH + colbase];
            const float4 w3 = *(const float4*)&Wout[(4 * k4 + 3) * CH + colbase];

            a0.x = fmaf(s0.x, w0.x, a0.x); a0.y = fmaf(s0.x, w0.y, a0.y);
            a0.z = fmaf(s0.x, w0.z, a0.z); a0.w = fmaf(s0.x, w0.w, a0.w);
            a0.x = fmaf(s0.y, w1.x, a0.x); a0.y = fmaf(s0.y, w1.y, a0.y);
            a0.z = fmaf(s0.y, w1.z, a0.z); a0.w = fmaf(s0.y, w1.w, a0.w);
            a0.x = fmaf(s0.z, w2.x, a0.x); a0.y = fmaf(s0.z, w2.y, a0.y);
            a0.z = fmaf(s0.z, w2.z, a0.z); a0.w = fmaf(s0.z, w2.w, a0.w);
            a0.x = fmaf(s0.w, w3.x, a0.x); a0.y = fmaf(s0.w, w3.y, a0.y);
            a0.z = fmaf(s0.w, w3.z, a0.z); a0.w = fmaf(s0.w, w3.w, a0.w);

            a1.x = fmaf(s1.x, w0.x, a1.x); a1.y = fmaf(s1.x, w0.y, a1.y);
            a1.z = fmaf(s1.x, w0.z, a1.z); a1.w = fmaf(s1.x, w0.w, a1.w);
            a1.x = fmaf(s1.y, w1.x, a1.x); a1.y = fmaf(s1.y, w1.y, a1.y);
            a1.z = fmaf(s1.y, w1.z, a1.z); a1.w = fmaf(s1.y, w1.w, a1.w);
            a1.x = fmaf(s1.z, w2.x, a1.x); a1.y = fmaf(s1.z, w2.y, a1.y);
            a1.z = fmaf(s1.z, w2.z, a1.z); a1.w = fmaf(s1.z, w2.w, a1.w);
            a1.x = fmaf(s1.w, w3.x, a1.x); a1.y = fmaf(s1.w, w3.y, a1.y);
            a1.z = fmaf(s1.w, w3.z, a1.z); a1.w = fmaf(s1.w, w3.w, a1.w);

            a2.x = fmaf(s2.x, w0.x, a2.x); a2.y = fmaf(s2.x, w0.y, a2.y);
            a2.z = fmaf(s2.x, w0.z, a2.z); a2.w = fmaf(s2.x, w0.w, a2.w);
            a2.x = fmaf(s2.y, w1.x, a2.x); a2.y = fmaf(s2.y, w1.y, a2.y);
            a2.z = fmaf(s2.y, w1.z, a2.z); a2.w = fmaf(s2.y, w1.w, a2.w);
            a2.x = fmaf(s2.z, w2.x, a2.x); a2.y = fmaf(s2.z, w2.y, a2.y);
            a2.z = fmaf(s2.z, w2.z, a2.z); a2.w = fmaf(s2.z, w2.w, a2.w);
            a2.x = fmaf(s2.w, w3.x, a2.x); a2.y = fmaf(s2.w, w3.y, a2.y);
            a2.z = fmaf(s2.w, w3.z, a2.z); a2.w = fmaf(s2.w, w3.w, a2.w);

            a3.x = fmaf(s3.x, w0.x, a3.x); a3.y = fmaf(s3.x, w0.y, a3.y);
            a3.z = fmaf(s3.x, w0.z, a3.z); a3.w = fmaf(s3.x, w0.w, a3.w);
            a3.x = fmaf(s3.y, w1.x, a3.x); a3.y = fmaf(s3.y, w1.y, a3.y);
            a3.z = fmaf(s3.y, w1.z, a3.z); a3.w = fmaf(s3.y, w1.w, a3.w);
            a3.x = fmaf(s3.z, w2.x, a3.x); a3.y = fmaf(s3.z, w2.y, a3.y);
            a3.z = fmaf(s3.z, w2.z, a3.z); a3.w = fmaf(s3.z, w2.w, a3.w);
            a3.x = fmaf(s3.w, w3.x, a3.x); a3.y = fmaf(s3.w, w3.y, a3.y);
            a3.z = fmaf(s3.w, w3.z, a3.z); a3.w = fmaf(s3.w, w3.w, a3.w);
        }

        float* ob = out + (size_t)(qb + qrow) * CH + colbase;
        *(float4*)(ob + 0 * CH) = a0;
        *(float4*)(ob + 1 * CH) = a1;
        *(float4*)(ob + 2 * CH) = a2;
        *(float4*)(ob + 3 * CH) = a3;
    }
}

} // namespace

extern "C" void kernel_launch(void* const* d_in, const int* in_sizes, int n_in,
                              void* d_out, int out_size)
{
    const float* query = (const float*)d_in[0];
    const float* value = (const float*)d_in[1];
    const float* qloc  = (const float*)d_in[2];
    const float* Woff  = (const float*)d_in[5];
    const float* boff  = (const float*)d_in[6];
    const float* Wattn = (const float*)d_in[7];
    const float* battn = (const float*)d_in[8];
    const float* Wout  = (const float*)d_in[9];
    const float* bout  = (const float*)d_in[10];

    constexpr int blocks = (BSZ * NQ) / QPC;     // 2048
    msda_fused<<<blocks, WARPS * 32>>>(query, value, qloc, Woff, boff,
                                       Wattn, battn, Wout, bout, (float*)d_out);
}

// round 7
// speedup vs baseline: 2.0752x; 1.2194x over previous
#include <cuda_runtime.h>
#include <cuda_fp16.h>

// Multi-scale deformable attention, fully fused (round 7).
// Fixed constants: BS=2, NQ=32768, C=128, NH=1, NL=2, NP=8
//   level 0: H=128,W=256,start=0 ; level 1: H=64,W=128,start=32768 ; NV=40960
//
// New this round: value tensor converted to fp16 scratch (halves gather
// wavefronts); Phase A/B deduplicated across lane halves.

namespace {

constexpr int BSZ   = 2;
constexpr int NQ    = 32768;
constexpr int CH    = 128;
constexpr int NV    = 40960;
constexpr int NSAMP = 16;   // NL*NP
constexpr int NOFF  = 32;   // NL*NP*2
constexpr int WARPS = 8;    // warps per CTA
constexpr int QPW   = 4;    // queries per warp
constexpr int QPC   = WARPS * QPW;   // 32 queries per CTA

constexpr size_t VAL_ELEMS = (size_t)BSZ * NV * CH;   // 10,485,760

__device__ __half g_val_h[VAL_ELEMS];                 // 21 MB scratch

// ---- value fp32 -> fp16 conversion (streamed, ~63 MB traffic) -------------
__global__ void __launch_bounds__(256) convert_value(const float* __restrict__ v)
{
    const size_t i = ((size_t)blockIdx.x * 256 + threadIdx.x) * 4;
    const float4 f = *(const float4*)(v + i);
    const __half2 h0 = __floats2half2_rn(f.x, f.y);
    const __half2 h1 = __floats2half2_rn(f.z, f.w);
    uint2 u;
    u.x = *(const unsigned int*)&h0;
    u.y = *(const unsigned int*)&h1;
    *(uint2*)(g_val_h + i) = u;
}

__global__ void __launch_bounds__(WARPS * 32, 4) msda_fused(
    const float* __restrict__ query,
    const float* __restrict__ qloc,
    const float* __restrict__ Woff,
    const float* __restrict__ boff,
    const float* __restrict__ Wattn,
    const float* __restrict__ battn,
    const float* __restrict__ Wout,
    const float* __restrict__ bout,
    float* __restrict__ out)
{
    // Dual-use buffer (16.5 KB), padded stride 33:
    //  Phase A: row q = query vector of CTA-query q
    //  Phase B: overwritten TRANSPOSED with sampled vecs (tbuf[k4][q])
    __shared__ float4 tbuf[QPC][33];
    // Per-warp sample records, one set per lane-half (2 queries in flight):
    // [h][s][0..3]=corner byte offsets, [h][s][4..7]=weights.   8 KB
    __shared__ float srec[WARPS][2][NSAMP][8];

    const int tid  = threadIdx.x;
    const int warp = tid >> 5;
    const int lane = tid & 31;
    const int j16  = lane & 15;     // sample owned by this lane
    const int qsel = lane >> 4;     // half 0 -> queries {0,1}, half 1 -> {2,3}
    const int qb   = blockIdx.x * QPC;
    const int q0   = qb + warp * QPW;
    const int b    = q0 >> 15;      // batch (uniform within CTA)

    // ---------------- Phase A: stage queries + deduplicated projections -----
    #pragma unroll
    for (int qq = 0; qq < QPW; qq++)
        tbuf[warp * QPW + qq][lane] =
            ((const float4*)(query + (size_t)(q0 + qq) * CH))[lane];
    __syncwarp();

    // Lane (h, j): (ox,oy) pair + attn logit of sample j for queries 2h+{0,1}.
    float2 offa[2];
    float  lg[2];
    {
        const float2 b2 = *(const float2*)&boff[2 * j16];
        const float  ba = battn[j16];
        offa[0] = b2; offa[1] = b2; lg[0] = ba; lg[1] = ba;
    }

    const int row0 = warp * QPW + 2 * qsel;

    #pragma unroll 4
    for (int k4 = 0; k4 < CH / 4; k4++) {
        const int k = 4 * k4;
        const float2 wo0 = *(const float2*)&Woff[(k + 0) * NOFF + 2 * j16];
        const float2 wo1 = *(const float2*)&Woff[(k + 1) * NOFF + 2 * j16];
        const float2 wo2 = *(const float2*)&Woff[(k + 2) * NOFF + 2 * j16];
        const float2 wo3 = *(const float2*)&Woff[(k + 3) * NOFF + 2 * j16];
        const float wa0 = Wattn[(k + 0) * NSAMP + j16];
        const float wa1 = Wattn[(k + 1) * NSAMP + j16];
        const float wa2 = Wattn[(k + 2) * NSAMP + j16];
        const float wa3 = Wattn[(k + 3) * NSAMP + j16];
        #pragma unroll
        for (int qq = 0; qq < 2; qq++) {
            const float4 qv = tbuf[row0 + qq][k4];   // 2 distinct rows/warp, 1 wf
            offa[qq].x = fmaf(qv.x, wo0.x, offa[qq].x);
            offa[qq].y = fmaf(qv.x, wo0.y, offa[qq].y);
            offa[qq].x = fmaf(qv.y, wo1.x, offa[qq].x);
            offa[qq].y = fmaf(qv.y, wo1.y, offa[qq].y);
            offa[qq].x = fmaf(qv.z, wo2.x, offa[qq].x);
            offa[qq].y = fmaf(qv.z, wo2.y, offa[qq].y);
            offa[qq].x = fmaf(qv.w, wo3.x, offa[qq].x);
            offa[qq].y = fmaf(qv.w, wo3.y, offa[qq].y);
            lg[qq] = fmaf(qv.x, wa0, lg[qq]);
            lg[qq] = fmaf(qv.y, wa1, lg[qq]);
            lg[qq] = fmaf(qv.z, wa2, lg[qq]);
            lg[qq] = fmaf(qv.w, wa3, lg[qq]);
        }
    }
    __syncthreads();    // all query-vector reads done before transposed stores

    // Level constants for the sample this lane owns.
    const int  l_own  = j16 >> 3;
    const int  Hl     = l_own ? 64 : 128;
    const int  Wl     = l_own ? 128 : 256;
    const int  startl = l_own ? 32768 : 0;
    const char* vb = (const char*)g_val_h + ((size_t)b * NV * CH + lane * 4) * 2;

    float (*recw)[NSAMP][8] = srec[warp];

    // ---------------- Phase B: 2 passes; each pass handles 2 queries --------
    #pragma unroll 1
    for (int t = 0; t < 2; t++) {
        __syncwarp();   // records of previous pass fully consumed

        // This lane's query for this pass:
        const int qi_own = q0 + 2 * qsel + t;

        // softmax over 16 samples within each lane-half (xor <=8 stays inside)
        float l0 = lg[t];
        float m = l0;
        #pragma unroll
        for (int o = 8; o >= 1; o >>= 1)
            m = fmaxf(m, __shfl_xor_sync(0xffffffffu, m, o));
        const float e = __expf(l0 - m);
        float se = e;
        #pragma unroll
        for (int o = 8; o >= 1; o >>= 1)
            se += __shfl_xor_sync(0xffffffffu, se, o);
        const float aw = e / se;

        // Per-lane sample record (32 sample-records across 2 queries at once).
        {
            const float4 lv = *(const float4*)(qloc + (size_t)qi_own * 4);
            const float x = (l_own ? lv.z : lv.x) * (float)Wl + offa[t].x - 0.5f;
            const float y = (l_own ? lv.w : lv.y) * (float)Hl + offa[t].y - 0.5f;
            const float xf = floorf(x), yf = floorf(y);
            const int   x0 = (int)xf,   y0 = (int)yf;
            const float lx = x - xf,    ly = y - yf;

            const bool vx0 = (unsigned)x0 < (unsigned)Wl;
            const bool vx1 = (unsigned)(x0 + 1) < (unsigned)Wl;
            const bool vy0 = (unsigned)y0 < (unsigned)Hl;
            const bool vy1 = (unsigned)(y0 + 1) < (unsigned)Hl;

            const float w00 = (vx0 && vy0) ? (1.f - lx) * (1.f - ly) * aw : 0.f;
            const float w10 = (vx1 && vy0) ? lx * (1.f - ly) * aw : 0.f;
            const float w01 = (vx0 && vy1) ? (1.f - lx) * ly * aw : 0.f;
            const float w11 = (vx1 && vy1) ? lx * ly * aw : 0.f;

            const int cx0 = min(max(x0, 0), Wl - 1);
            const int cx1 = min(max(x0 + 1, 0), Wl - 1);
            const int cy0 = min(max(y0, 0), Hl - 1) * Wl + startl;
            const int cy1 = min(max(y0 + 1, 0), Hl - 1) * Wl + startl;

            // fp16 rows: 256 B per value row
            const int o00 = (cy0 + cx0) << 8;
            const int o10 = (cy0 + cx1) << 8;
            const int o01 = (cy1 + cx0) << 8;
            const int o11 = (cy1 + cx1) << 8;

            // every lane writes a unique slot: [qsel][j16]
            *(float4*)&recw[qsel][j16][0] = make_float4(
                __int_as_float(o00), __int_as_float(o10),
                __int_as_float(o01), __int_as_float(o11));
            *(float4*)&recw[qsel][j16][4] = make_float4(w00, w10, w01, w11);
        }
        __syncwarp();

        // Gather both queries of this pass (full warp each, fp16 values).
        #pragma unroll
        for (int g = 0; g < 2; g++) {
            float ac0 = 0.f, ac1 = 0.f, ac2 = 0.f, ac3 = 0.f;
            #pragma unroll
            for (int s = 0; s < NSAMP; s++) {
                const float4 ro = *(const float4*)&recw[g][s][0];  // broadcast
                const float4 rw = *(const float4*)&recw[g][s][4];  // broadcast
                const uint2 u00 = *(const uint2*)(vb + __float_as_int(ro.x));
                const uint2 u10 = *(const uint2*)(vb + __float_as_int(ro.y));
                const uint2 u01 = *(const uint2*)(vb + __float_as_int(ro.z));
                const uint2 u11 = *(const uint2*)(vb + __float_as_int(ro.w));

                const float2 a00 = __half22float2(*(const __half2*)&u00.x);
                const float2 b00 = __half22float2(*(const __half2*)&u00.y);
                const float2 a10 = __half22float2(*(const __half2*)&u10.x);
                const float2 b10 = __half22float2(*(const __half2*)&u10.y);
                const float2 a01 = __half22float2(*(const __half2*)&u01.x);
                const float2 b01 = __half22float2(*(const __half2*)&u01.y);
                const float2 a11 = __half22float2(*(const __half2*)&u11.x);
                const float2 b11 = __half22float2(*(const __half2*)&u11.y);

                ac0 = fmaf(rw.x, a00.x, ac0); ac1 = fmaf(rw.x, a00.y, ac1);
                ac2 = fmaf(rw.x, b00.x, ac2); ac3 = fmaf(rw.x, b00.y, ac3);
                ac0 = fmaf(rw.y, a10.x, ac0); ac1 = fmaf(rw.y, a10.y, ac1);
                ac2 = fmaf(rw.y, b10.x, ac2); ac3 = fmaf(rw.y, b10.y, ac3);
                ac0 = fmaf(rw.z, a01.x, ac0); ac1 = fmaf(rw.z, a01.y, ac1);
                ac2 = fmaf(rw.z, b01.x, ac2); ac3 = fmaf(rw.z, b01.y, ac3);
                ac0 = fmaf(rw.w, a11.x, ac0); ac1 = fmaf(rw.w, a11.y, ac1);
                ac2 = fmaf(rw.w, b11.x, ac2); ac3 = fmaf(rw.w, b11.y, ac3);
            }
            // transposed stash: tbuf[k4=lane][query 2g+t]
            tbuf[lane][warp * QPW + 2 * g + t] = make_float4(ac0, ac1, ac2, ac3);
        }
    }
    __syncthreads();    // all sampled vectors visible CTA-wide

    // ---------------- Phase C: CTA-cooperative output projection ------------
    // Warp w owns output cols [16w,16w+16).  Lane tile: 4 queries x 4 cols.
    {
        const int qg = lane >> 2;               // query group 0..7
        const int cg = lane & 3;                // col group  0..3
        const int colbase = warp * 16 + cg * 4;
        const int qrow = 4 * qg;

        const float4 bo = *(const float4*)&bout[colbase];
        float4 a0 = bo, a1 = bo, a2 = bo, a3 = bo;

        #pragma unroll 2
        for (int k4 = 0; k4 < CH / 4; k4++) {
            const float4 s0 = tbuf[k4][qrow + 0];
            const float4 s1 = tbuf[k4][qrow + 1];
            const float4 s2 = tbuf[k4][qrow + 2];
            const float4 s3 = tbuf[k4][qrow + 3];
            const float4 w0 = *(const float4*)&Wout[(4 * k4 + 0) * CH + colbase];
            const float4 w1 = *(const float4*)&Wout[(4 * k4 + 1) * CH + colbase];
            const float4 w2 = *(const float4*)&Wout[(4 * k4 + 2) * CH + colbase];
            const float4 w3 = *(const float4*)&Wout[(4 * k4 + 3) * CH + colbase];

            a0.x = fmaf(s0.x, w0.x, a0.x); a0.y = fmaf(s0.x, w0.y, a0.y);
            a0.z = fmaf(s0.x, w0.z, a0.z); a0.w = fmaf(s0.x, w0.w, a0.w);
            a0.x = fmaf(s0.y, w1.x, a0.x); a0.y = fmaf(s0.y, w1.y, a0.y);
            a0.z = fmaf(s0.y, w1.z, a0.z); a0.w = fmaf(s0.y, w1.w, a0.w);
            a0.x = fmaf(s0.z, w2.x, a0.x); a0.y = fmaf(s0.z, w2.y, a0.y);
            a0.z = fmaf(s0.z, w2.z, a0.z); a0.w = fmaf(s0.z, w2.w, a0.w);
            a0.x = fmaf(s0.w, w3.x, a0.x); a0.y = fmaf(s0.w, w3.y, a0.y);
            a0.z = fmaf(s0.w, w3.z, a0.z); a0.w = fmaf(s0.w, w3.w, a0.w);

            a1.x = fmaf(s1.x, w0.x, a1.x); a1.y = fmaf(s1.x, w0.y, a1.y);
            a1.z = fmaf(s1.x, w0.z, a1.z); a1.w = fmaf(s1.x, w0.w, a1.w);
            a1.x = fmaf(s1.y, w1.x, a1.x); a1.y = fmaf(s1.y, w1.y, a1.y);
            a1.z = fmaf(s1.y, w1.z, a1.z); a1.w = fmaf(s1.y, w1.w, a1.w);
            a1.x = fmaf(s1.z, w2.x, a1.x); a1.y = fmaf(s1.z, w2.y, a1.y);
            a1.z = fmaf(s1.z, w2.z, a1.z); a1.w = fmaf(s1.z, w2.w, a1.w);
            a1.x = fmaf(s1.w, w3.x, a1.x); a1.y = fmaf(s1.w, w3.y, a1.y);
            a1.z = fmaf(s1.w, w3.z, a1.z); a1.w = fmaf(s1.w, w3.w, a1.w);

            a2.x = fmaf(s2.x, w0.x, a2.x); a2.y = fmaf(s2.x, w0.y, a2.y);
            a2.z = fmaf(s2.x, w0.z, a2.z); a2.w = fmaf(s2.x, w0.w, a2.w);
            a2.x = fmaf(s2.y, w1.x, a2.x); a2.y = fmaf(s2.y, w1.y, a2.y);
            a2.z = fmaf(s2.y, w1.z, a2.z); a2.w = fmaf(s2.y, w1.w, a2.w);
            a2.x = fmaf(s2.z, w2.x, a2.x); a2.y = fmaf(s2.z, w2.y, a2.y);
            a2.z = fmaf(s2.z, w2.z, a2.z); a2.w = fmaf(s2.z, w2.w, a2.w);
            a2.x = fmaf(s2.w, w3.x, a2.x); a2.y = fmaf(s2.w, w3.y, a2.y);
            a2.z = fmaf(s2.w, w3.z, a2.z); a2.w = fmaf(s2.w, w3.w, a2.w);

            a3.x = fmaf(s3.x, w0.x, a3.x); a3.y = fmaf(s3.x, w0.y, a3.y);
            a3.z = fmaf(s3.x, w0.z, a3.z); a3.w = fmaf(s3.x, w0.w, a3.w);
            a3.x = fmaf(s3.y, w1.x, a3.x); a3.y = fmaf(s3.y, w1.y, a3.y);
            a3.z = fmaf(s3.y, w1.z, a3.z); a3.w = fmaf(s3.y, w1.w, a3.w);
            a3.x = fmaf(s3.z, w2.x, a3.x); a3.y = fmaf(s3.z, w2.y, a3.y);
            a3.z = fmaf(s3.z, w2.z, a3.z); a3.w = fmaf(s3.z, w2.w, a3.w);
            a3.x = fmaf(s3.w, w3.x, a3.x); a3.y = fmaf(s3.w, w3.y, a3.y);
            a3.z = fmaf(s3.w, w3.z, a3.z); a3.w = fmaf(s3.w, w3.w, a3.w);
        }

        float* ob = out + (size_t)(qb + qrow) * CH + colbase;
        *(float4*)(ob + 0 * CH) = a0;
        *(float4*)(ob + 1 * CH) = a1;
        *(float4*)(ob + 2 * CH) = a2;
        *(float4*)(ob + 3 * CH) = a3;
    }
}

} // namespace

extern "C" void kernel_launch(void* const* d_in, const int* in_sizes, int n_in,
                              void* d_out, int out_size)
{
    const float* query = (const float*)d_in[0];
    const float* value = (const float*)d_in[1];
    const float* qloc  = (const float*)d_in[2];
    const float* Woff  = (const float*)d_in[5];
    const float* boff  = (const float*)d_in[6];
    const float* Wattn = (const float*)d_in[7];
    const float* battn = (const float*)d_in[8];
    const float* Wout  = (const float*)d_in[9];
    const float* bout  = (const float*)d_in[10];

    // value fp32 -> fp16 scratch (every call; graph-capturable)
    constexpr int conv_blocks = (int)(VAL_ELEMS / 4 / 256);   // 10240
    convert_value<<<conv_blocks, 256>>>(value);

    constexpr int blocks = (BSZ * NQ) / QPC;     // 2048
    msda_fused<<<blocks, WARPS * 32>>>(query, qloc, Woff, boff,
                                       Wattn, battn, Wout, bout, (float*)d_out);
}

// round 8
// speedup vs baseline: 2.0912x; 1.0077x over previous
#include <cuda_runtime.h>
#include <cuda_fp16.h>

// Multi-scale deformable attention, fully fused (round 8).
// Fixed constants: BS=2, NQ=32768, C=128, NH=1, NL=2, NP=8
//   level 0: H=128,W=256,start=0 ; level 1: H=64,W=128,start=32768 ; NV=40960
//
// R8: half-warp LDG.128 gather (halves LSU instr), pre-packed fp16
//     projection-weight table (Phase A loads 10 -> 4 per k4).

namespace {

constexpr int BSZ   = 2;
constexpr int NQ    = 32768;
constexpr int CH    = 128;
constexpr int NV    = 40960;
constexpr int NSAMP = 16;   // NL*NP
constexpr int NOFF  = 32;   // NL*NP*2
constexpr int WARPS = 8;    // warps per CTA
constexpr int QPW   = 4;    // queries per warp
constexpr int QPC   = WARPS * QPW;   // 32 queries per CTA

constexpr size_t VAL_ELEMS = (size_t)BSZ * NV * CH;   // 10,485,760

__device__ __half g_val_h[VAL_ELEMS];                 // 21 MB scratch
// Packed projection weights: [k/2][sample j] = 8 fp16:
//   {offx(k0,j), offy(k0,j), attn(k0,j), 0, offx(k1,j), offy(k1,j), attn(k1,j), 0}
__device__ uint4 g_wpack[CH / 2][NSAMP];

// ---- value fp32 -> fp16 conversion (streamed, ~63 MB traffic) -------------
__global__ void __launch_bounds__(256) convert_value(const float* __restrict__ v)
{
    const size_t i = ((size_t)blockIdx.x * 256 + threadIdx.x) * 4;
    const float4 f = *(const float4*)(v + i);
    const __half2 h0 = __floats2half2_rn(f.x, f.y);
    const __half2 h1 = __floats2half2_rn(f.z, f.w);
    uint2 u;
    u.x = *(const unsigned int*)&h0;
    u.y = *(const unsigned int*)&h1;
    *(uint2*)(g_val_h + i) = u;
}

// ---- projection-weight packing (1024 threads, one-shot) --------------------
__global__ void __launch_bounds__(256) pack_weights(
    const float* __restrict__ Woff, const float* __restrict__ Wattn)
{
    const int idx = blockIdx.x * 256 + threadIdx.x;   // 0..1023
    const int k2 = idx >> 4;
    const int j  = idx & 15;
    const int k0 = 2 * k2, k1 = 2 * k2 + 1;
    const __half2 h0 = __floats2half2_rn(Woff[k0 * NOFF + 2 * j], Woff[k0 * NOFF + 2 * j + 1]);
    const __half2 h1 = __floats2half2_rn(Wattn[k0 * NSAMP + j], 0.f);
    const __half2 h2 = __floats2half2_rn(Woff[k1 * NOFF + 2 * j], Woff[k1 * NOFF + 2 * j + 1]);
    const __half2 h3 = __floats2half2_rn(Wattn[k1 * NSAMP + j], 0.f);
    uint4 u;
    u.x = *(const unsigned int*)&h0;
    u.y = *(const unsigned int*)&h1;
    u.z = *(const unsigned int*)&h2;
    u.w = *(const unsigned int*)&h3;
    g_wpack[k2][j] = u;
}

// Accumulate 8 fp16 channels (one uint4) with weight w into fp32 ac[8].
__device__ __forceinline__ void acc8(float* ac, float w, const uint4& u)
{
    const float2 c0 = __half22float2(*(const __half2*)&u.x);
    const float2 c1 = __half22float2(*(const __half2*)&u.y);
    const float2 c2 = __half22float2(*(const __half2*)&u.z);
    const float2 c3 = __half22float2(*(const __half2*)&u.w);
    ac[0] = fmaf(w, c0.x, ac[0]); ac[1] = fmaf(w, c0.y, ac[1]);
    ac[2] = fmaf(w, c1.x, ac[2]); ac[3] = fmaf(w, c1.y, ac[3]);
    ac[4] = fmaf(w, c2.x, ac[4]); ac[5] = fmaf(w, c2.y, ac[5]);
    ac[6] = fmaf(w, c3.x, ac[6]); ac[7] = fmaf(w, c3.y, ac[7]);
}

__global__ void __launch_bounds__(WARPS * 32, 4) msda_fused(
    const float* __restrict__ query,
    const float* __restrict__ qloc,
    const float* __restrict__ boff,
    const float* __restrict__ battn,
    const float* __restrict__ Wout,
    const float* __restrict__ bout,
    float* __restrict__ out)
{
    // Dual-use buffer, padded stride 33:
    //  Phase A: row q = query vector of CTA-query q
    //  Phase B: overwritten TRANSPOSED with sampled vecs (tbuf[k4][q])
    __shared__ float4 tbuf[QPC][33];
    // Per-warp sample records, one set per lane-half:
    // [h][s][0..3]=corner byte offsets, [h][s][4..7]=weights.
    __shared__ float srec[WARPS][2][NSAMP][8];

    const int tid  = threadIdx.x;
    const int warp = tid >> 5;
    const int lane = tid & 31;
    const int j16  = lane & 15;     // sample / channel-chunk owned by this lane
    const int qsel = lane >> 4;     // half 0 -> queries {0,1}, half 1 -> {2,3}
    const int qb   = blockIdx.x * QPC;
    const int q0   = qb + warp * QPW;
    const int b    = q0 >> 15;      // batch (uniform within CTA)

    // ---------------- Phase A: stage queries + packed-weight projections ----
    #pragma unroll
    for (int qq = 0; qq < QPW; qq++)
        tbuf[warp * QPW + qq][lane] =
            ((const float4*)(query + (size_t)(q0 + qq) * CH))[lane];
    __syncwarp();

    float2 offa[2];
    float  lg[2];
    {
        const float2 b2 = *(const float2*)&boff[2 * j16];
        const float  ba = battn[j16];
        offa[0] = b2; offa[1] = b2; lg[0] = ba; lg[1] = ba;
    }

    const int row0 = warp * QPW + 2 * qsel;

    #pragma unroll 4
    for (int k4 = 0; k4 < CH / 4; k4++) {
        const uint4 wp0 = g_wpack[2 * k4 + 0][j16];   // k = 4k4, 4k4+1
        const uint4 wp1 = g_wpack[2 * k4 + 1][j16];   // k = 4k4+2, 4k4+3
        const float2 o0 = __half22float2(*(const __half2*)&wp0.x);
        const float  a0 = __half2float(__low2half(*(const __half2*)&wp0.y));
        const float2 o1 = __half22float2(*(const __half2*)&wp0.z);
        const float  a1 = __half2float(__low2half(*(const __half2*)&wp0.w));
        const float2 o2 = __half22float2(*(const __half2*)&wp1.x);
        const float  a2 = __half2float(__low2half(*(const __half2*)&wp1.y));
        const float2 o3 = __half22float2(*(const __half2*)&wp1.z);
        const float  a3 = __half2float(__low2half(*(const __half2*)&wp1.w));
        #pragma unroll
        for (int qq = 0; qq < 2; qq++) {
            const float4 qv = tbuf[row0 + qq][k4];
            offa[qq].x = fmaf(qv.x, o0.x, offa[qq].x);
            offa[qq].y = fmaf(qv.x, o0.y, offa[qq].y);
            lg[qq]     = fmaf(qv.x, a0,   lg[qq]);
            offa[qq].x = fmaf(qv.y, o1.x, offa[qq].x);
            offa[qq].y = fmaf(qv.y, o1.y, offa[qq].y);
            lg[qq]     = fmaf(qv.y, a1,   lg[qq]);
            offa[qq].x = fmaf(qv.z, o2.x, offa[qq].x);
            offa[qq].y = fmaf(qv.z, o2.y, offa[qq].y);
            lg[qq]     = fmaf(qv.z, a2,   lg[qq]);
            offa[qq].x = fmaf(qv.w, o3.x, offa[qq].x);
            offa[qq].y = fmaf(qv.w, o3.y, offa[qq].y);
            lg[qq]     = fmaf(qv.w, a3,   lg[qq]);
        }
    }
    __syncthreads();    // all query-vector reads done before transposed stores

    // Level constants for the sample this lane owns.
    const int  l_own  = j16 >> 3;
    const int  Hl     = l_own ? 64 : 128;
    const int  Wl     = l_own ? 128 : 256;
    const int  startl = l_own ? 32768 : 0;
    // Gather base: this lane covers fp16 channels [8*j16, 8*j16+8)
    const char* vbh = (const char*)g_val_h + (size_t)b * NV * CH * 2 + j16 * 16;

    float (*recw)[NSAMP][8] = srec[warp];

    // ---------------- Phase B: 2 passes; each half gathers its own query ----
    #pragma unroll 1
    for (int t = 0; t < 2; t++) {
        __syncwarp();   // records of previous pass fully consumed

        const int qi_own = q0 + 2 * qsel + t;

        // softmax over 16 samples within each lane-half
        float l0 = lg[t];
        float m = l0;
        #pragma unroll
        for (int o = 8; o >= 1; o >>= 1)
            m = fmaxf(m, __shfl_xor_sync(0xffffffffu, m, o));
        const float e = __expf(l0 - m);
        float se = e;
        #pragma unroll
        for (int o = 8; o >= 1; o >>= 1)
            se += __shfl_xor_sync(0xffffffffu, se, o);
        const float aw = e / se;

        // Per-lane sample record (32 records across 2 queries at once).
        {
            const float4 lv = *(const float4*)(qloc + (size_t)qi_own * 4);
            const float x = (l_own ? lv.z : lv.x) * (float)Wl + offa[t].x - 0.5f;
            const float y = (l_own ? lv.w : lv.y) * (float)Hl + offa[t].y - 0.5f;
            const float xf = floorf(x), yf = floorf(y);
            const int   x0 = (int)xf,   y0 = (int)yf;
            const float lx = x - xf,    ly = y - yf;

            const bool vx0 = (unsigned)x0 < (unsigned)Wl;
            const bool vx1 = (unsigned)(x0 + 1) < (unsigned)Wl;
            const bool vy0 = (unsigned)y0 < (unsigned)Hl;
            const bool vy1 = (unsigned)(y0 + 1) < (unsigned)Hl;

            const float w00 = (vx0 && vy0) ? (1.f - lx) * (1.f - ly) * aw : 0.f;
            const float w10 = (vx1 && vy0) ? lx * (1.f - ly) * aw : 0.f;
            const float w01 = (vx0 && vy1) ? (1.f - lx) * ly * aw : 0.f;
            const float w11 = (vx1 && vy1) ? lx * ly * aw : 0.f;

            const int cx0 = min(max(x0, 0), Wl - 1);
            const int cx1 = min(max(x0 + 1, 0), Wl - 1);
            const int cy0 = min(max(y0, 0), Hl - 1) * Wl + startl;
            const int cy1 = min(max(y0 + 1, 0), Hl - 1) * Wl + startl;

            const int o00 = (cy0 + cx0) << 8;   // 256 B per fp16 value row
            const int o10 = (cy0 + cx1) << 8;
            const int o01 = (cy1 + cx0) << 8;
            const int o11 = (cy1 + cx1) << 8;

            *(float4*)&recw[qsel][j16][0] = make_float4(
                __int_as_float(o00), __int_as_float(o10),
                __int_as_float(o01), __int_as_float(o11));
            *(float4*)&recw[qsel][j16][4] = make_float4(w00, w10, w01, w11);
        }
        __syncwarp();

        // Gather: each half loads full 256B corner rows with LDG.128.
        float ac[8] = {0.f, 0.f, 0.f, 0.f, 0.f, 0.f, 0.f, 0.f};
        #pragma unroll
        for (int s = 0; s < NSAMP; s++) {
            const float4 ro = *(const float4*)&recw[qsel][s][0];
            const float4 rw = *(const float4*)&recw[qsel][s][4];
            const uint4 u00 = *(const uint4*)(vbh + __float_as_int(ro.x));
            const uint4 u10 = *(const uint4*)(vbh + __float_as_int(ro.y));
            const uint4 u01 = *(const uint4*)(vbh + __float_as_int(ro.z));
            const uint4 u11 = *(const uint4*)(vbh + __float_as_int(ro.w));
            acc8(ac, rw.x, u00);
            acc8(ac, rw.y, u10);
            acc8(ac, rw.z, u01);
            acc8(ac, rw.w, u11);
        }

        // Transposed stash: lane owns channels 8*j16.. -> rows k4 = 2*j16, +1.
        const int qidx = warp * QPW + 2 * qsel + t;
        tbuf[2 * j16 + 0][qidx] = make_float4(ac[0], ac[1], ac[2], ac[3]);
        tbuf[2 * j16 + 1][qidx] = make_float4(ac[4], ac[5], ac[6], ac[7]);
    }
    __syncthreads();    // all sampled vectors visible CTA-wide

    // ---------------- Phase C: CTA-cooperative output projection ------------
    // Warp w owns output cols [16w,16w+16).  Lane tile: 4 queries x 4 cols.
    {
        const int qg = lane >> 2;               // query group 0..7
        const int cg = lane & 3;                // col group  0..3
        const int colbase = warp * 16 + cg * 4;
        const int qrow = 4 * qg;

        const float4 bo = *(const float4*)&bout[colbase];
        float4 a0 = bo, a1 = bo, a2 = bo, a3 = bo;

        #pragma unroll 2
        for (int k4 = 0; k4 < CH / 4; k4++) {
            const float4 s0 = tbuf[k4][qrow + 0];
            const float4 s1 = tbuf[k4][qrow + 1];
            const float4 s2 = tbuf[k4][qrow + 2];
            const float4 s3 = tbuf[k4][qrow + 3];
            const float4 w0 = *(const float4*)&Wout[(4 * k4 + 0) * CH + colbase];
            const float4 w1 = *(const float4*)&Wout[(4 * k4 + 1) * CH + colbase];
            const float4 w2 = *(const float4*)&Wout[(4 * k4 + 2) * CH + colbase];
            const float4 w3 = *(const float4*)&Wout[(4 * k4 + 3) * CH + colbase];

            a0.x = fmaf(s0.x, w0.x, a0.x); a0.y = fmaf(s0.x, w0.y, a0.y);
            a0.z = fmaf(s0.x, w0.z, a0.z); a0.w = fmaf(s0.x, w0.w, a0.w);
            a0.x = fmaf(s0.y, w1.x, a0.x); a0.y = fmaf(s0.y, w1.y, a0.y);
            a0.z = fmaf(s0.y, w1.z, a0.z); a0.w = fmaf(s0.y, w1.w, a0.w);
            a0.x = fmaf(s0.z, w2.x, a0.x); a0.y = fmaf(s0.z, w2.y, a0.y);
            a0.z = fmaf(s0.z, w2.z, a0.z); a0.w = fmaf(s0.z, w2.w, a0.w);
            a0.x = fmaf(s0.w, w3.x, a0.x); a0.y = fmaf(s0.w, w3.y, a0.y);
            a0.z = fmaf(s0.w, w3.z, a0.z); a0.w = fmaf(s0.w, w3.w, a0.w);

            a1.x = fmaf(s1.x, w0.x, a1.x); a1.y = fmaf(s1.x, w0.y, a1.y);
            a1.z = fmaf(s1.x, w0.z, a1.z); a1.w = fmaf(s1.x, w0.w, a1.w);
            a1.x = fmaf(s1.y, w1.x, a1.x); a1.y = fmaf(s1.y, w1.y, a1.y);
            a1.z = fmaf(s1.y, w1.z, a1.z); a1.w = fmaf(s1.y, w1.w, a1.w);
            a1.x = fmaf(s1.z, w2.x, a1.x); a1.y = fmaf(s1.z, w2.y, a1.y);
            a1.z = fmaf(s1.z, w2.z, a1.z); a1.w = fmaf(s1.z, w2.w, a1.w);
            a1.x = fmaf(s1.w, w3.x, a1.x); a1.y = fmaf(s1.w, w3.y, a1.y);
            a1.z = fmaf(s1.w, w3.z, a1.z); a1.w = fmaf(s1.w, w3.w, a1.w);

            a2.x = fmaf(s2.x, w0.x, a2.x); a2.y = fmaf(s2.x, w0.y, a2.y);
            a2.z = fmaf(s2.x, w0.z, a2.z); a2.w = fmaf(s2.x, w0.w, a2.w);
            a2.x = fmaf(s2.y, w1.x, a2.x); a2.y = fmaf(s2.y, w1.y, a2.y);
            a2.z = fmaf(s2.y, w1.z, a2.z); a2.w = fmaf(s2.y, w1.w, a2.w);
            a2.x = fmaf(s2.z, w2.x, a2.x); a2.y = fmaf(s2.z, w2.y, a2.y);
            a2.z = fmaf(s2.z, w2.z, a2.z); a2.w = fmaf(s2.z, w2.w, a2.w);
            a2.x = fmaf(s2.w, w3.x, a2.x); a2.y = fmaf(s2.w, w3.y, a2.y);
            a2.z = fmaf(s2.w, w3.z, a2.z); a2.w = fmaf(s2.w, w3.w, a2.w);

            a3.x = fmaf(s3.x, w0.x, a3.x); a3.y = fmaf(s3.x, w0.y, a3.y);
            a3.z = fmaf(s3.x, w0.z, a3.z); a3.w = fmaf(s3.x, w0.w, a3.w);
            a3.x = fmaf(s3.y, w1.x, a3.x); a3.y = fmaf(s3.y, w1.y, a3.y);
            a3.z = fmaf(s3.y, w1.z, a3.z); a3.w = fmaf(s3.y, w1.w, a3.w);
            a3.x = fmaf(s3.z, w2.x, a3.x); a3.y = fmaf(s3.z, w2.y, a3.y);
            a3.z = fmaf(s3.z, w2.z, a3.z); a3.w = fmaf(s3.z, w2.w, a3.w);
            a3.x = fmaf(s3.w, w3.x, a3.x); a3.y = fmaf(s3.w, w3.y, a3.y);
            a3.z = fmaf(s3.w, w3.z, a3.z); a3.w = fmaf(s3.w, w3.w, a3.w);
        }

        float* ob = out + (size_t)(qb + qrow) * CH + colbase;
        *(float4*)(ob + 0 * CH) = a0;
        *(float4*)(ob + 1 * CH) = a1;
        *(float4*)(ob + 2 * CH) = a2;
        *(float4*)(ob + 3 * CH) = a3;
    }
}

} // namespace

extern "C" void kernel_launch(void* const* d_in, const int* in_sizes, int n_in,
                              void* d_out, int out_size)
{
    const float* query = (const float*)d_in[0];
    const float* value = (const float*)d_in[1];
    const float* qloc  = (const float*)d_in[2];
    const float* Woff  = (const float*)d_in[5];
    const float* boff  = (const float*)d_in[6];
    const float* Wattn = (const float*)d_in[7];
    const float* battn = (const float*)d_in[8];
    const float* Wout  = (const float*)d_in[9];
    const float* bout  = (const float*)d_in[10];

    // One-shot prep (re-run every call; graph-capturable, deterministic)
    pack_weights<<<4, 256>>>(Woff, Wattn);
    constexpr int conv_blocks = (int)(VAL_ELEMS / 4 / 256);   // 10240
    convert_value<<<conv_blocks, 256>>>(value);

    constexpr int blocks = (BSZ * NQ) / QPC;     // 2048
    msda_fused<<<blocks, WARPS * 32>>>(query, qloc, boff, battn,
                                       Wout, bout, (float*)d_out);
}

// round 9
// speedup vs baseline: 2.2857x; 1.0930x over previous
#include <cuda_runtime.h>
#include <cuda_fp16.h>

// Multi-scale deformable attention, fully fused (round 9).
// Fixed constants: BS=2, NQ=32768, C=128, NH=1, NL=2, NP=8
//   level 0: H=128,W=256,start=0 ; level 1: H=64,W=128,start=32768 ; NV=40960
//
// R9: fp32x2 packed FMA (fma.rn.f32x2) in gather / Phase A / Phase C to halve
//     the FFMA-pipe issue floor; pack_weights merged into convert_value.

namespace {

constexpr int BSZ   = 2;
constexpr int NQ    = 32768;
constexpr int CH    = 128;
constexpr int NV    = 40960;
constexpr int NSAMP = 16;   // NL*NP
constexpr int NOFF  = 32;   // NL*NP*2
constexpr int WARPS = 8;    // warps per CTA
constexpr int QPW   = 4;    // queries per warp
constexpr int QPC   = WARPS * QPW;   // 32 queries per CTA

constexpr size_t VAL_ELEMS = (size_t)BSZ * NV * CH;   // 10,485,760

typedef unsigned long long ull;

__device__ __half g_val_h[VAL_ELEMS];                 // 21 MB scratch
// Packed projection weights: [k/2][sample j] = 8 fp16:
//   {offx(k0,j), offy(k0,j), attn(k0,j), 0, offx(k1,j), offy(k1,j), attn(k1,j), 0}
__device__ uint4 g_wpack[CH / 2][NSAMP];

// ---- f32x2 helpers ---------------------------------------------------------
__device__ __forceinline__ ull pack2(float lo, float hi)
{
    ull r;
    asm("mov.b64 %0, {%1, %2};" : "=l"(r) : "f"(lo), "f"(hi));
    return r;
}
__device__ __forceinline__ float2 unpack2(ull v)
{
    float2 f;
    asm("mov.b64 {%0, %1}, %2;" : "=f"(f.x), "=f"(f.y) : "l"(v));
    return f;
}
__device__ __forceinline__ void fma2(ull& acc, ull a, ull b)
{
    asm("fma.rn.f32x2 %0, %1, %2, %0;" : "+l"(acc) : "l"(a), "l"(b));
}
// half2 (as u32) -> packed f32x2 (as u64)
__device__ __forceinline__ ull h2f2(unsigned int h)
{
    ull r;
    asm("{\n\t"
        ".reg .f16 lo, hi;\n\t"
        ".reg .f32 flo, fhi;\n\t"
        "mov.b32 {lo, hi}, %1;\n\t"
        "cvt.f32.f16 flo, lo;\n\t"
        "cvt.f32.f16 fhi, hi;\n\t"
        "mov.b64 %0, {flo, fhi};\n\t"
        "}"
        : "=l"(r) : "r"(h));
    return r;
}

// ---- value fp32 -> fp16 conversion + weight packing (fused prep) -----------
__global__ void __launch_bounds__(256) convert_value(
    const float* __restrict__ v,
    const float* __restrict__ Woff, const float* __restrict__ Wattn)
{
    const size_t i = ((size_t)blockIdx.x * 256 + threadIdx.x) * 4;
    const float4 f = *(const float4*)(v + i);
    const __half2 h0 = __floats2half2_rn(f.x, f.y);
    const __half2 h1 = __floats2half2_rn(f.z, f.w);
    uint2 u;
    u.x = *(const unsigned int*)&h0;
    u.y = *(const unsigned int*)&h1;
    *(uint2*)(g_val_h + i) = u;

    if (blockIdx.x == 0) {
        for (int idx = threadIdx.x; idx < (CH / 2) * NSAMP; idx += 256) {
            const int k2 = idx >> 4;
            const int j  = idx & 15;
            const int k0 = 2 * k2, k1 = 2 * k2 + 1;
            const __half2 a0 = __floats2half2_rn(Woff[k0 * NOFF + 2 * j],
                                                 Woff[k0 * NOFF + 2 * j + 1]);
            const __half2 a1 = __floats2half2_rn(Wattn[k0 * NSAMP + j], 0.f);
            const __half2 a2 = __floats2half2_rn(Woff[k1 * NOFF + 2 * j],
                                                 Woff[k1 * NOFF + 2 * j + 1]);
            const __half2 a3 = __floats2half2_rn(Wattn[k1 * NSAMP + j], 0.f);
            uint4 w;
            w.x = *(const unsigned int*)&a0;
            w.y = *(const unsigned int*)&a1;
            w.z = *(const unsigned int*)&a2;
            w.w = *(const unsigned int*)&a3;
            g_wpack[k2][j] = w;
        }
    }
}

// Accumulate 8 fp16 channels (one uint4) with weight w into 4 packed f32x2.
__device__ __forceinline__ void acc8p(ull* ac, float w, const uint4& u)
{
    const ull wd = pack2(w, w);
    fma2(ac[0], wd, h2f2(u.x));
    fma2(ac[1], wd, h2f2(u.y));
    fma2(ac[2], wd, h2f2(u.z));
    fma2(ac[3], wd, h2f2(u.w));
}

__global__ void __launch_bounds__(WARPS * 32, 4) msda_fused(
    const float* __restrict__ query,
    const float* __restrict__ qloc,
    const float* __restrict__ boff,
    const float* __restrict__ battn,
    const float* __restrict__ Wout,
    const float* __restrict__ bout,
    float* __restrict__ out)
{
    // Dual-use buffer, padded stride 33:
    //  Phase A: row q = query vector of CTA-query q
    //  Phase B: overwritten TRANSPOSED with sampled vecs (tbuf[k4][q])
    __shared__ float4 tbuf[QPC][33];
    // Per-warp sample records, one set per lane-half:
    // [h][s][0..3]=corner byte offsets, [h][s][4..7]=weights.
    __shared__ float srec[WARPS][2][NSAMP][8];

    const int tid  = threadIdx.x;
    const int warp = tid >> 5;
    const int lane = tid & 31;
    const int j16  = lane & 15;     // sample / channel-chunk owned by this lane
    const int qsel = lane >> 4;     // half 0 -> queries {0,1}, half 1 -> {2,3}
    const int qb   = blockIdx.x * QPC;
    const int q0   = qb + warp * QPW;
    const int b    = q0 >> 15;      // batch (uniform within CTA)

    // ---------------- Phase A: stage queries + packed-weight projections ----
    #pragma unroll
    for (int qq = 0; qq < QPW; qq++)
        tbuf[warp * QPW + qq][lane] =
            ((const float4*)(query + (size_t)(q0 + qq) * CH))[lane];
    __syncwarp();

    ull   offp[2];                  // packed (ox, oy) accumulators
    float lg[2];
    {
        const float2 b2 = *(const float2*)&boff[2 * j16];
        const float  ba = battn[j16];
        offp[0] = pack2(b2.x, b2.y);
        offp[1] = offp[0];
        lg[0] = ba; lg[1] = ba;
    }

    const int row0 = warp * QPW + 2 * qsel;

    #pragma unroll 4
    for (int k4 = 0; k4 < CH / 4; k4++) {
        const uint4 wp0 = g_wpack[2 * k4 + 0][j16];   // k = 4k4, 4k4+1
        const uint4 wp1 = g_wpack[2 * k4 + 1][j16];   // k = 4k4+2, 4k4+3
        const ull o0 = h2f2(wp0.x);
        const ull o1 = h2f2(wp0.z);
        const ull o2 = h2f2(wp1.x);
        const ull o3 = h2f2(wp1.z);
        const float a0 = __half2float(__low2half(*(const __half2*)&wp0.y));
        const float a1 = __half2float(__low2half(*(const __half2*)&wp0.w));
        const float a2 = __half2float(__low2half(*(const __half2*)&wp1.y));
        const float a3 = __half2float(__low2half(*(const __half2*)&wp1.w));
        #pragma unroll
        for (int qq = 0; qq < 2; qq++) {
            const float4 qv = tbuf[row0 + qq][k4];
            fma2(offp[qq], pack2(qv.x, qv.x), o0);
            lg[qq] = fmaf(qv.x, a0, lg[qq]);
            fma2(offp[qq], pack2(qv.y, qv.y), o1);
            lg[qq] = fmaf(qv.y, a1, lg[qq]);
            fma2(offp[qq], pack2(qv.z, qv.z), o2);
            lg[qq] = fmaf(qv.z, a2, lg[qq]);
            fma2(offp[qq], pack2(qv.w, qv.w), o3);
            lg[qq] = fmaf(qv.w, a3, lg[qq]);
        }
    }
    __syncthreads();    // all query-vector reads done before transposed stores

    // Level constants for the sample this lane owns.
    const int  l_own  = j16 >> 3;
    const int  Hl     = l_own ? 64 : 128;
    const int  Wl     = l_own ? 128 : 256;
    const int  startl = l_own ? 32768 : 0;
    // Gather base: this lane covers fp16 channels [8*j16, 8*j16+8)
    const char* vbh = (const char*)g_val_h + (size_t)b * NV * CH * 2 + j16 * 16;

    float (*recw)[NSAMP][8] = srec[warp];

    // ---------------- Phase B: 2 passes; each half gathers its own query ----
    #pragma unroll 1
    for (int t = 0; t < 2; t++) {
        __syncwarp();   // records of previous pass fully consumed

        const int qi_own = q0 + 2 * qsel + t;

        // softmax over 16 samples within each lane-half
        float l0 = lg[t];
        float m = l0;
        #pragma unroll
        for (int o = 8; o >= 1; o >>= 1)
            m = fmaxf(m, __shfl_xor_sync(0xffffffffu, m, o));
        const float e = __expf(l0 - m);
        float se = e;
        #pragma unroll
        for (int o = 8; o >= 1; o >>= 1)
            se += __shfl_xor_sync(0xffffffffu, se, o);
        const float aw = e / se;

        // Per-lane sample record (32 records across 2 queries at once).
        {
            const float2 ofa = unpack2(offp[t]);
            const float4 lv = *(const float4*)(qloc + (size_t)qi_own * 4);
            const float x = (l_own ? lv.z : lv.x) * (float)Wl + ofa.x - 0.5f;
            const float y = (l_own ? lv.w : lv.y) * (float)Hl + ofa.y - 0.5f;
            const float xf = floorf(x), yf = floorf(y);
            const int   x0 = (int)xf,   y0 = (int)yf;
            const float lx = x - xf,    ly = y - yf;

            const bool vx0 = (unsigned)x0 < (unsigned)Wl;
            const bool vx1 = (unsigned)(x0 + 1) < (unsigned)Wl;
            const bool vy0 = (unsigned)y0 < (unsigned)Hl;
            const bool vy1 = (unsigned)(y0 + 1) < (unsigned)Hl;

            const float w00 = (vx0 && vy0) ? (1.f - lx) * (1.f - ly) * aw : 0.f;
            const float w10 = (vx1 && vy0) ? lx * (1.f - ly) * aw : 0.f;
            const float w01 = (vx0 && vy1) ? (1.f - lx) * ly * aw : 0.f;
            const float w11 = (vx1 && vy1) ? lx * ly * aw : 0.f;

            const int cx0 = min(max(x0, 0), Wl - 1);
            const int cx1 = min(max(x0 + 1, 0), Wl - 1);
            const int cy0 = min(max(y0, 0), Hl - 1) * Wl + startl;
            const int cy1 = min(max(y0 + 1, 0), Hl - 1) * Wl + startl;

            const int o00 = (cy0 + cx0) << 8;   // 256 B per fp16 value row
            const int o10 = (cy0 + cx1) << 8;
            const int o01 = (cy1 + cx0) << 8;
            const int o11 = (cy1 + cx1) << 8;

            *(float4*)&recw[qsel][j16][0] = make_float4(
                __int_as_float(o00), __int_as_float(o10),
                __int_as_float(o01), __int_as_float(o11));
            *(float4*)&recw[qsel][j16][4] = make_float4(w00, w10, w01, w11);
        }
        __syncwarp();

        // Gather: each half loads full 256B corner rows with LDG.128.
        ull ac[4];
        ac[0] = ac[1] = ac[2] = ac[3] = pack2(0.f, 0.f);
        #pragma unroll
        for (int s = 0; s < NSAMP; s++) {
            const float4 ro = *(const float4*)&recw[qsel][s][0];
            const float4 rw = *(const float4*)&recw[qsel][s][4];
            const uint4 u00 = *(const uint4*)(vbh + __float_as_int(ro.x));
            const uint4 u10 = *(const uint4*)(vbh + __float_as_int(ro.y));
            const uint4 u01 = *(const uint4*)(vbh + __float_as_int(ro.z));
            const uint4 u11 = *(const uint4*)(vbh + __float_as_int(ro.w));
            acc8p(ac, rw.x, u00);
            acc8p(ac, rw.y, u10);
            acc8p(ac, rw.z, u01);
            acc8p(ac, rw.w, u11);
        }

        // Transposed stash: lane owns channels 8*j16.. -> rows k4 = 2*j16, +1.
        const int qidx = warp * QPW + 2 * qsel + t;
        const float2 p0 = unpack2(ac[0]);
        const float2 p1 = unpack2(ac[1]);
        const float2 p2 = unpack2(ac[2]);
        const float2 p3 = unpack2(ac[3]);
        tbuf[2 * j16 + 0][qidx] = make_float4(p0.x, p0.y, p1.x, p1.y);
        tbuf[2 * j16 + 1][qidx] = make_float4(p2.x, p2.y, p3.x, p3.y);
    }
    __syncthreads();    // all sampled vectors visible CTA-wide

    // ---------------- Phase C: CTA-cooperative output projection ------------
    // Warp w owns output cols [16w,16w+16).  Lane tile: 4 queries x 4 cols.
    {
        const int qg = lane >> 2;               // query group 0..7
        const int cg = lane & 3;                // col group  0..3
        const int colbase = warp * 16 + cg * 4;
        const int qrow = 4 * qg;

        const float4 bo = *(const float4*)&bout[colbase];
        // a_lo[q] = packed cols {0,1}; a_hi[q] = packed cols {2,3}
        ull a_lo[4], a_hi[4];
        #pragma unroll
        for (int q = 0; q < 4; q++) {
            a_lo[q] = pack2(bo.x, bo.y);
            a_hi[q] = pack2(bo.z, bo.w);
        }

        #pragma unroll 2
        for (int k4 = 0; k4 < CH / 4; k4++) {
            const float4 s0 = tbuf[k4][qrow + 0];
            const float4 s1 = tbuf[k4][qrow + 1];
            const float4 s2 = tbuf[k4][qrow + 2];
            const float4 s3 = tbuf[k4][qrow + 3];
            // W_out row pairs as pre-packed f32x2 (free: just a 16B load)
            const ulonglong2 w0 = *(const ulonglong2*)&Wout[(4 * k4 + 0) * CH + colbase];
            const ulonglong2 w1 = *(const ulonglong2*)&Wout[(4 * k4 + 1) * CH + colbase];
            const ulonglong2 w2 = *(const ulonglong2*)&Wout[(4 * k4 + 2) * CH + colbase];
            const ulonglong2 w3 = *(const ulonglong2*)&Wout[(4 * k4 + 3) * CH + colbase];

            ull d;
            d = pack2(s0.x, s0.x); fma2(a_lo[0], d, w0.x); fma2(a_hi[0], d, w0.y);
            d = pack2(s0.y, s0.y); fma2(a_lo[0], d, w1.x); fma2(a_hi[0], d, w1.y);
            d = pack2(s0.z, s0.z); fma2(a_lo[0], d, w2.x); fma2(a_hi[0], d, w2.y);
            d = pack2(s0.w, s0.w); fma2(a_lo[0], d, w3.x); fma2(a_hi[0], d, w3.y);

            d = pack2(s1.x, s1.x); fma2(a_lo[1], d, w0.x); fma2(a_hi[1], d, w0.y);
            d = pack2(s1.y, s1.y); fma2(a_lo[1], d, w1.x); fma2(a_hi[1], d, w1.y);
            d = pack2(s1.z, s1.z); fma2(a_lo[1], d, w2.x); fma2(a_hi[1], d, w2.y);
            d = pack2(s1.w, s1.w); fma2(a_lo[1], d, w3.x); fma2(a_hi[1], d, w3.y);

            d = pack2(s2.x, s2.x); fma2(a_lo[2], d, w0.x); fma2(a_hi[2], d, w0.y);
            d = pack2(s2.y, s2.y); fma2(a_lo[2], d, w1.x); fma2(a_hi[2], d, w1.y);
            d = pack2(s2.z, s2.z); fma2(a_lo[2], d, w2.x); fma2(a_hi[2], d, w2.y);
            d = pack2(s2.w, s2.w); fma2(a_lo[2], d, w3.x); fma2(a_hi[2], d, w3.y);

            d = pack2(s3.x, s3.x); fma2(a_lo[3], d, w0.x); fma2(a_hi[3], d, w0.y);
            d = pack2(s3.y, s3.y); fma2(a_lo[3], d, w1.x); fma2(a_hi[3], d, w1.y);
            d = pack2(s3.z, s3.z); fma2(a_lo[3], d, w2.x); fma2(a_hi[3], d, w2.y);
            d = pack2(s3.w, s3.w); fma2(a_lo[3], d, w3.x); fma2(a_hi[3], d, w3.y);
        }

        float* ob = out + (size_t)(qb + qrow) * CH + colbase;
        #pragma unroll
        for (int q = 0; q < 4; q++) {
            const float2 lo = unpack2(a_lo[q]);
            const float2 hi = unpack2(a_hi[q]);
            *(float4*)(ob + q * CH) = make_float4(lo.x, lo.y, hi.x, hi.y);
        }
    }
}

} // namespace

extern "C" void kernel_launch(void* const* d_in, const int* in_sizes, int n_in,
                              void* d_out, int out_size)
{
    const float* query = (const float*)d_in[0];
    const float* value = (const float*)d_in[1];
    const float* qloc  = (const float*)d_in[2];
    const float* Woff  = (const float*)d_in[5];
    const float* boff  = (const float*)d_in[6];
    const float* Wattn = (const float*)d_in[7];
    const float* battn = (const float*)d_in[8];
    const float* Wout  = (const float*)d_in[9];
    const float* bout  = (const float*)d_in[10];

    // Fused prep: value fp32 -> fp16 + projection-weight packing
    constexpr int conv_blocks = (int)(VAL_ELEMS / 4 / 256);   // 10240
    convert_value<<<conv_blocks, 256>>>(value, Woff, Wattn);

    constexpr int blocks = (BSZ * NQ) / QPC;     // 2048
    msda_fused<<<blocks, WARPS * 32>>>(query, qloc, boff, battn,
                                       Wout, bout, (float*)d_out);
}